// round 1
// baseline (speedup 1.0000x reference)
#include <cuda_runtime.h>
#include <cuda_bf16.h>
#include <math.h>

// ---------------------------------------------------------------------------
// ConvTransBlock: B=2, H=W=256, C=256 (CD=128 conv, TD=128 trans), WS=8,
// NH=4 heads, HD=32.  fp32 baseline pipeline, 11 kernel launches.
// ---------------------------------------------------------------------------

#define M_TOK 131072            // B*H*W

// Scratch (device globals; allocation at module load, sanctioned by harness)
__device__ float g_y  [131072 * 256];  // conv1 output  [M,256]
__device__ float g_r  [131072 * 128];  // conv3x3 intermediate
__device__ float g_cx [131072 * 128];  // conv path output
__device__ float g_ln [131072 * 128];  // layernorm output (reused)
__device__ float g_qkv[131072 * 384];  // qkv
__device__ float g_att[131072 * 128];  // attention out (pre-proj)
__device__ float g_t  [131072 * 128];  // trans path after proj residual
__device__ float g_u  [131072 * 512];  // mlp hidden
__device__ float g_t2 [131072 * 128];  // trans path final

// ---------------------------------------------------------------------------
// Generic tiled GEMM: C[M,N] = A[M,K] @ W[K,N] + bias (+epilogue)
// 64x64 tile, BK=16, 256 threads, 4x4 per thread.
// EPI: 0 = bias only, 1 = bias+gelu, 2 = bias+residual
// CONCAT: A = concat(A0[M,128], A1[M,128]) along K
// ---------------------------------------------------------------------------
template<int EPI, bool CONCAT>
__global__ void __launch_bounds__(256) gemm_k(
    const float* __restrict__ A0, const float* __restrict__ A1, int strideA,
    const float* __restrict__ W,  const float* __restrict__ bias,
    const float* __restrict__ res, int res_stride,
    float* __restrict__ out, int K, int N)
{
    __shared__ float As[16][64];
    __shared__ float Bs[16][64];

    const int m0 = blockIdx.x * 64;
    const int n0 = blockIdx.y * 64;
    const int tid = threadIdx.x;
    const int ty = tid >> 4, tx = tid & 15;

    const int arow = tid >> 2;          // 0..63
    const int ak4  = (tid & 3) * 4;     // 0,4,8,12
    const int wr   = tid >> 4;          // 0..15
    const int wc4  = (tid & 15) * 4;    // 0..60

    float acc[4][4] = {};

    for (int k0 = 0; k0 < K; k0 += 16) {
        // --- load A tile (transposed into As[k][m]) ---
        const float* ap;
        int kg = k0 + ak4;
        if (CONCAT) {
            if (kg < 128) ap = A0 + (size_t)(m0 + arow) * 128 + kg;
            else          ap = A1 + (size_t)(m0 + arow) * 128 + (kg - 128);
        } else {
            ap = A0 + (size_t)(m0 + arow) * strideA + kg;
        }
        float4 av = *(const float4*)ap;
        As[ak4 + 0][arow] = av.x;
        As[ak4 + 1][arow] = av.y;
        As[ak4 + 2][arow] = av.z;
        As[ak4 + 3][arow] = av.w;
        // --- load W tile ---
        float4 wv = *(const float4*)(W + (size_t)(k0 + wr) * N + n0 + wc4);
        *(float4*)&Bs[wr][wc4] = wv;
        __syncthreads();

        #pragma unroll
        for (int kk = 0; kk < 16; kk++) {
            float4 a4 = *(float4*)&As[kk][ty * 4];
            float4 b4 = *(float4*)&Bs[kk][tx * 4];
            float ar[4] = {a4.x, a4.y, a4.z, a4.w};
            float br[4] = {b4.x, b4.y, b4.z, b4.w};
            #pragma unroll
            for (int i = 0; i < 4; i++)
                #pragma unroll
                for (int j = 0; j < 4; j++)
                    acc[i][j] += ar[i] * br[j];
        }
        __syncthreads();
    }

    // --- epilogue ---
    const int n = n0 + tx * 4;
    float4 bv = *(const float4*)(bias + n);
    #pragma unroll
    for (int i = 0; i < 4; i++) {
        int m = m0 + ty * 4 + i;
        float v[4] = {acc[i][0] + bv.x, acc[i][1] + bv.y,
                      acc[i][2] + bv.z, acc[i][3] + bv.w};
        if (EPI == 1) {
            #pragma unroll
            for (int j = 0; j < 4; j++)
                v[j] = 0.5f * v[j] * (1.0f + erff(v[j] * 0.7071067811865476f));
        }
        if (EPI == 2) {
            float4 rv = *(const float4*)(res + (size_t)m * res_stride + n);
            v[0] += rv.x; v[1] += rv.y; v[2] += rv.z; v[3] += rv.w;
        }
        float4 o4 = {v[0], v[1], v[2], v[3]};
        *(float4*)(out + (size_t)m * N + n) = o4;
    }
}

// ---------------------------------------------------------------------------
// Conv3x3 (SAME, zero pad), 128->128 channels, implicit GEMM.
// Block: one 8x8 spatial tile x all 128 output channels. 256 threads.
// Epilogue: lrelu; if RES: + 2*res[pix*256+co] (conv_x residual).
// ---------------------------------------------------------------------------
template<bool RES>
__global__ void __launch_bounds__(256) conv3_k(
    const float* __restrict__ in, int in_stride,
    const float* __restrict__ wgt, const float* __restrict__ bias,
    const float* __restrict__ res, float* __restrict__ out)
{
    __shared__ float sin_[64][17];
    __shared__ float sw[16][128];

    const int tid = threadIdx.x;
    const int bb = blockIdx.x >> 10;
    const int th = (blockIdx.x >> 5) & 31;
    const int tw = blockIdx.x & 31;
    const int gh0 = th * 8, gw0 = tw * 8;

    const int tc  = tid & 15;        // channel group -> co = tc*8 .. +7
    const int tp4 = (tid >> 4) * 4;  // pixel base   -> pixels tp4 .. tp4+3

    const int lp  = tid >> 2;        // load pixel 0..63
    const int lc4 = (tid & 3) * 4;   // load ci 0,4,8,12
    const int py = lp >> 3, px = lp & 7;

    float acc[4][8] = {};

    for (int tap = 0; tap < 9; tap++) {
        const int dy = tap / 3 - 1, dx = tap % 3 - 1;
        const int ih = gh0 + py + dy, iw = gw0 + px + dx;
        const bool ok = ((unsigned)ih < 256u) && ((unsigned)iw < 256u);
        const float* ibase = in + (size_t)((bb * 256 + ih) * 256 + iw) * in_stride;

        for (int c0 = 0; c0 < 128; c0 += 16) {
            float4 v = ok ? *(const float4*)(ibase + c0 + lc4)
                          : make_float4(0.f, 0.f, 0.f, 0.f);
            sin_[lp][lc4 + 0] = v.x;
            sin_[lp][lc4 + 1] = v.y;
            sin_[lp][lc4 + 2] = v.z;
            sin_[lp][lc4 + 3] = v.w;
            #pragma unroll
            for (int j = 0; j < 2; j++) {
                int e4 = tid * 2 + j;
                int kr = e4 >> 5, co4 = (e4 & 31) * 4;
                *(float4*)&sw[kr][co4] =
                    *(const float4*)(wgt + (size_t)(tap * 128 + c0 + kr) * 128 + co4);
            }
            __syncthreads();

            #pragma unroll
            for (int ci = 0; ci < 16; ci++) {
                float4 wa = *(float4*)&sw[ci][tc * 8];
                float4 wb = *(float4*)&sw[ci][tc * 8 + 4];
                #pragma unroll
                for (int p = 0; p < 4; p++) {
                    float a = sin_[tp4 + p][ci];
                    acc[p][0] += a * wa.x; acc[p][1] += a * wa.y;
                    acc[p][2] += a * wa.z; acc[p][3] += a * wa.w;
                    acc[p][4] += a * wb.x; acc[p][5] += a * wb.y;
                    acc[p][6] += a * wb.z; acc[p][7] += a * wb.w;
                }
            }
            __syncthreads();
        }
    }

    // epilogue
    #pragma unroll
    for (int p = 0; p < 4; p++) {
        const int pp = tp4 + p;
        const int gh = gh0 + (pp >> 3), gw = gw0 + (pp & 7);
        const size_t pix = (size_t)((bb * 256 + gh) * 256 + gw);
        #pragma unroll
        for (int c = 0; c < 8; c++) {
            const int co = tc * 8 + c;
            float v = acc[p][c] + bias[co];
            v = v >= 0.f ? v : 0.01f * v;
            if (RES) v += 2.0f * res[pix * 256 + co];
            out[pix * 128 + co] = v;
        }
    }
}

// ---------------------------------------------------------------------------
// LayerNorm over last dim (128). One warp per token.
// ---------------------------------------------------------------------------
__global__ void __launch_bounds__(256) ln_k(
    const float* __restrict__ in, int stride,
    const float* __restrict__ g, const float* __restrict__ b,
    float* __restrict__ out)
{
    const int token = blockIdx.x * 8 + (threadIdx.x >> 5);
    const int lane = threadIdx.x & 31;
    const float* p = in + (size_t)token * stride;
    float4 v = *(const float4*)(p + lane * 4);
    float s  = v.x + v.y + v.z + v.w;
    float sq = v.x * v.x + v.y * v.y + v.z * v.z + v.w * v.w;
    #pragma unroll
    for (int o = 16; o; o >>= 1) {
        s  += __shfl_xor_sync(0xffffffffu, s,  o);
        sq += __shfl_xor_sync(0xffffffffu, sq, o);
    }
    const float mu  = s * (1.0f / 128.0f);
    const float var = sq * (1.0f / 128.0f) - mu * mu;
    const float rs  = rsqrtf(var + 1e-5f);
    float4 gv = *(const float4*)(g + lane * 4);
    float4 bv = *(const float4*)(b + lane * 4);
    float4 o4;
    o4.x = (v.x - mu) * rs * gv.x + bv.x;
    o4.y = (v.y - mu) * rs * gv.y + bv.y;
    o4.z = (v.z - mu) * rs * gv.z + bv.z;
    o4.w = (v.w - mu) * rs * gv.w + bv.w;
    *(float4*)(out + (size_t)token * 128 + lane * 4) = o4;
}

// ---------------------------------------------------------------------------
// Windowed attention: one block per (batch, window, head).
// Rolls cancel: gather qkv at ((hh+4)&255,(ww+4)&255) and write back to the
// same spatial address. Shift mask from rolled-coord regions (248/252 bounds).
// ---------------------------------------------------------------------------
__global__ void __launch_bounds__(256) attn_k(
    const float* __restrict__ qkv, const float* __restrict__ rpb,
    float* __restrict__ outp)
{
    __shared__ float qs[64][32];
    __shared__ float ks[64][33];
    __shared__ float vs[64][33];
    __shared__ float Ps[64][65];
    __shared__ int pixS[64];
    __shared__ int ridS[64];

    const int tid = threadIdx.x;
    const int head = blockIdx.x & 3;
    const int w = (blockIdx.x >> 2) & 1023;
    const int b = blockIdx.x >> 12;
    const int wi = w >> 5, wj = w & 31;

    if (tid < 64) {
        const int ti = tid >> 3, tj = tid & 7;
        const int hh = wi * 8 + ti, ww = wj * 8 + tj;
        const int h  = (hh + 4) & 255, w_ = (ww + 4) & 255;
        pixS[tid] = (b * 256 + h) * 256 + w_;
        const int rh = hh < 248 ? 0 : (hh < 252 ? 1 : 2);
        const int rw = ww < 248 ? 0 : (ww < 252 ? 1 : 2);
        ridS[tid] = rh * 3 + rw;
    }
    __syncthreads();

    const int ho = head * 32;
    for (int idx = tid; idx < 2048; idx += 256) {
        const int t = idx >> 5, d = idx & 31;
        const size_t base = (size_t)pixS[t] * 384 + ho + d;
        qs[t][d] = qkv[base];
        ks[t][d] = qkv[base + 128];
        vs[t][d] = qkv[base + 256];
    }
    __syncthreads();

    const int warp = tid >> 5, lane = tid & 31;
    #pragma unroll
    for (int rr = 0; rr < 8; rr++) {
        const int r = warp * 8 + rr;
        float s0 = 0.f, s1 = 0.f;
        #pragma unroll
        for (int d = 0; d < 32; d++) {
            const float qv = qs[r][d];
            s0 += qv * ks[lane][d];
            s1 += qv * ks[lane + 32][d];
        }
        const int ri = r >> 3, rj = r & 7;
        const int rid_r = ridS[r];
        // col c0 = lane
        {
            const int c = lane;
            const int ci = c >> 3, cj = c & 7;
            const int rel = (ri - ci + 7) * 15 + (rj - cj + 7);
            s0 = s0 * 0.17677669529663687f + rpb[rel * 4 + head];
            if (rid_r != ridS[c]) s0 -= 1e9f;
        }
        // col c1 = lane+32
        {
            const int c = lane + 32;
            const int ci = c >> 3, cj = c & 7;
            const int rel = (ri - ci + 7) * 15 + (rj - cj + 7);
            s1 = s1 * 0.17677669529663687f + rpb[rel * 4 + head];
            if (rid_r != ridS[c]) s1 -= 1e9f;
        }
        float mx = fmaxf(s0, s1);
        #pragma unroll
        for (int o = 16; o; o >>= 1) mx = fmaxf(mx, __shfl_xor_sync(0xffffffffu, mx, o));
        float e0 = expf(s0 - mx), e1 = expf(s1 - mx);
        float sm = e0 + e1;
        #pragma unroll
        for (int o = 16; o; o >>= 1) sm += __shfl_xor_sync(0xffffffffu, sm, o);
        const float inv = 1.0f / sm;
        Ps[r][lane] = e0 * inv;
        Ps[r][lane + 32] = e1 * inv;
    }
    __syncthreads();

    // P @ V
    const int i = tid >> 2, d0 = (tid & 3) * 8;
    float acc[8] = {};
    #pragma unroll
    for (int j = 0; j < 64; j++) {
        const float p = Ps[i][j];
        #pragma unroll
        for (int dd = 0; dd < 8; dd++) acc[dd] += p * vs[j][d0 + dd];
    }
    const size_t ob = (size_t)pixS[i] * 128 + ho + d0;
    #pragma unroll
    for (int dd = 0; dd < 8; dd++) outp[ob + dd] = acc[dd];
}

// ---------------------------------------------------------------------------
extern "C" void kernel_launch(void* const* d_in, const int* in_sizes, int n_in,
                              void* d_out, int out_size)
{
    const float* x    = (const float*)d_in[0];
    const float* c1w  = (const float*)d_in[1];
    const float* c1b  = (const float*)d_in[2];
    const float* rw1  = (const float*)d_in[3];
    const float* rb1  = (const float*)d_in[4];
    const float* rw2  = (const float*)d_in[5];
    const float* rb2  = (const float*)d_in[6];
    const float* ln1g = (const float*)d_in[7];
    const float* ln1b = (const float*)d_in[8];
    const float* qkvw = (const float*)d_in[9];
    const float* qkvb = (const float*)d_in[10];
    const float* rpb  = (const float*)d_in[11];
    const float* pw   = (const float*)d_in[12];
    const float* pb   = (const float*)d_in[13];
    const float* ln2g = (const float*)d_in[14];
    const float* ln2b = (const float*)d_in[15];
    const float* mw1  = (const float*)d_in[16];
    const float* mb1  = (const float*)d_in[17];
    const float* mw2  = (const float*)d_in[18];
    const float* mb2  = (const float*)d_in[19];
    const float* c2w  = (const float*)d_in[20];
    const float* c2b  = (const float*)d_in[21];
    float* out = (float*)d_out;

    float *y, *r, *cx, *ln, *qkv, *att, *t, *u, *t2;
    cudaGetSymbolAddress((void**)&y,   g_y);
    cudaGetSymbolAddress((void**)&r,   g_r);
    cudaGetSymbolAddress((void**)&cx,  g_cx);
    cudaGetSymbolAddress((void**)&ln,  g_ln);
    cudaGetSymbolAddress((void**)&qkv, g_qkv);
    cudaGetSymbolAddress((void**)&att, g_att);
    cudaGetSymbolAddress((void**)&t,   g_t);
    cudaGetSymbolAddress((void**)&u,   g_u);
    cudaGetSymbolAddress((void**)&t2,  g_t2);

    const int M = M_TOK;
    dim3 thr(256);

    // 1. conv1x1 #1: y = x @ c1w + c1b               [M,256]
    gemm_k<0,false><<<dim3(M/64, 4), thr>>>(x, nullptr, 256, c1w, c1b,
                                            nullptr, 0, y, 256, 256);
    // 2. conv3x3 #1 + lrelu:  r = lrelu(conv(y[:,:128]))
    conv3_k<false><<<2048, thr>>>(y, 256, rw1, rb1, nullptr, r);
    // 3. conv3x3 #2 + lrelu + 2*conv_x:  cx
    conv3_k<true><<<2048, thr>>>(r, 128, rw2, rb2, y, cx);
    // 4. LN1 on trans_x = y[:,128:]
    ln_k<<<M/8, thr>>>(y + 128, 256, ln1g, ln1b, ln);
    // 5. qkv = ln @ qkvw + qkvb                      [M,384]
    gemm_k<0,false><<<dim3(M/64, 6), thr>>>(ln, nullptr, 128, qkvw, qkvb,
                                            nullptr, 0, qkv, 128, 384);
    // 6. windowed attention (rolls folded into gather/scatter)
    attn_k<<<8192, thr>>>(qkv, rpb, att);
    // 7. proj + residual: t = att @ pw + pb + trans_x
    gemm_k<2,false><<<dim3(M/64, 2), thr>>>(att, nullptr, 128, pw, pb,
                                            y + 128, 256, t, 128, 128);
    // 8. LN2
    ln_k<<<M/8, thr>>>(t, 128, ln2g, ln2b, ln);
    // 9. mlp1 + gelu: u = gelu(ln @ mw1 + mb1)       [M,512]
    gemm_k<1,false><<<dim3(M/64, 8), thr>>>(ln, nullptr, 128, mw1, mb1,
                                            nullptr, 0, u, 128, 512);
    // 10. mlp2 + residual: t2 = u @ mw2 + mb2 + t
    gemm_k<2,false><<<dim3(M/64, 2), thr>>>(u, nullptr, 512, mw2, mb2,
                                            t, 128, t2, 512, 128);
    // 11. conv1x1 #2 on concat(cx, t2) + x -> out
    gemm_k<2,true><<<dim3(M/64, 4), thr>>>(cx, t2, 0, c2w, c2b,
                                           x, 256, out, 256, 256);
}

// round 3
// speedup vs baseline: 2.1785x; 2.1785x over previous
#include <cuda_runtime.h>
#include <cuda_bf16.h>
#include <math.h>
#include <stdint.h>

// ===========================================================================
// ConvTransBlock via legacy tensor-core path (mma.sync bf16, hi/lo split).
// B=2, H=W=256, C=256 (CD=128 | TD=128), WS=8, NH=4, HD=32.
// ===========================================================================

#define M_TOK 131072

// ---------------- fp32 buffers ----------------
__device__ float g_y  [131072 * 256];   // conv1 out
__device__ float g_qkv[131072 * 384];
__device__ float g_t  [131072 * 128];   // trans after proj residual

// ---------------- bf16 hi/lo activation buffers ----------------
__device__ __nv_bfloat16 g_xh[131072*256], g_xl[131072*256];
__device__ __nv_bfloat16 g_yh[131072*128], g_yl[131072*128];   // conv half of y
__device__ __nv_bfloat16 g_rh[131072*128], g_rl[131072*128];
__device__ __nv_bfloat16 g_ch[131072*128], g_cl[131072*128];   // cx
__device__ __nv_bfloat16 g_lh[131072*128], g_ll[131072*128];   // ln out
__device__ __nv_bfloat16 g_ah[131072*128], g_al[131072*128];   // attn out
__device__ __nv_bfloat16 g_uh[131072*512], g_ul[131072*512];   // mlp hidden
__device__ __nv_bfloat16 g_th[131072*128], g_tl[131072*128];   // t2

// transposed bf16 weights (hi / lo), K-major rows per n
#define WT_TOTAL 622592
__device__ __align__(256) __nv_bfloat16 g_wth[WT_TOTAL];
__device__ __align__(256) __nv_bfloat16 g_wtl[WT_TOTAL];
#define OFF_C1   0
#define OFF_RW1  65536
#define OFF_RW2  212992
#define OFF_QKV  360448
#define OFF_PW   409600
#define OFF_MW1  425984
#define OFF_MW2  491520
#define OFF_C2   557056

// ---------------- PTX helpers (all sm_80-compatible) ----------------
__device__ __forceinline__ uint32_t smem_u32(const void* p) {
    uint32_t a;
    asm("{ .reg .u64 t; cvta.to.shared.u64 t, %1; cvt.u32.u64 %0, t; }" : "=r"(a) : "l"(p));
    return a;
}
#define CP_ASYNC(dst, src, sz) \
    asm volatile("cp.async.cg.shared.global [%0], [%1], 16, %2;" \
        :: "r"(dst), "l"(src), "r"(sz))
#define CP_COMMIT() asm volatile("cp.async.commit_group;")
#define CP_WAIT(n)  asm volatile("cp.async.wait_group %0;" :: "n"(n))
#define LDM4(r, addr) \
    asm volatile("ldmatrix.sync.aligned.m8n8.x4.shared.b16 {%0,%1,%2,%3}, [%4];" \
        : "=r"((r)[0]), "=r"((r)[1]), "=r"((r)[2]), "=r"((r)[3]) : "r"(addr))
#define MMA(d, a, b0, b1) \
    asm volatile("mma.sync.aligned.m16n8k16.row.col.f32.bf16.bf16.f32 " \
        "{%0,%1,%2,%3}, {%4,%5,%6,%7}, {%8,%9}, {%0,%1,%2,%3};" \
        : "+f"((d)[0]), "+f"((d)[1]), "+f"((d)[2]), "+f"((d)[3]) \
        : "r"((a)[0]), "r"((a)[1]), "r"((a)[2]), "r"((a)[3]), "r"(b0), "r"(b1))

__device__ __forceinline__ uint32_t pack_bf2(float a, float b) {
    __nv_bfloat16 ha = __float2bfloat16(a), hb = __float2bfloat16(b);
    return ((uint32_t)__bfloat16_as_ushort(hb) << 16) | (uint32_t)__bfloat16_as_ushort(ha);
}

// ---------------- weight prep: W[k][n] -> Wt[n][k] bf16 hi/lo ----------------
struct PrepArgs { const float* src[8]; int K[8], N[8], off[8]; };
__global__ void __launch_bounds__(256) prep_k(PrepArgs a,
    __nv_bfloat16* __restrict__ dh, __nv_bfloat16* __restrict__ dl)
{
    int w = blockIdx.y;
    int K = a.K[w], N = a.N[w];
    int idx = blockIdx.x * 256 + threadIdx.x;
    if (idx >= K * N) return;
    int n = idx / K, k = idx - n * K;
    float v = a.src[w][(size_t)k * N + n];
    __nv_bfloat16 h = __float2bfloat16(v);
    dh[a.off[w] + idx] = h;
    dl[a.off[w] + idx] = __float2bfloat16(v - __bfloat162float(h));
}

// ---------------- fp32 -> bf16 hi/lo converter (for x) ----------------
__global__ void __launch_bounds__(256) cvt_k(const float* __restrict__ in,
    __nv_bfloat16* __restrict__ oh, __nv_bfloat16* __restrict__ ol, int n4)
{
    int i = blockIdx.x * 256 + threadIdx.x;
    if (i >= n4) return;
    float4 v = ((const float4*)in)[i];
    float h0 = __bfloat162float(__float2bfloat16(v.x));
    float h1 = __bfloat162float(__float2bfloat16(v.y));
    float h2 = __bfloat162float(__float2bfloat16(v.z));
    float h3 = __bfloat162float(__float2bfloat16(v.w));
    uint2 H = make_uint2(pack_bf2(v.x, v.y), pack_bf2(v.z, v.w));
    uint2 L = make_uint2(pack_bf2(v.x - h0, v.y - h1), pack_bf2(v.z - h2, v.w - h3));
    ((uint2*)oh)[i] = H;
    ((uint2*)ol)[i] = L;
}

// ---------------- unified tensor-core GEMM / implicit-GEMM conv ----------------
// MODE: 0 gemm, 1 concat(A0bf,A1bf) along K, 2 conv3x3 (A = [M,128] bf16, halo)
// EPI:  0 bias; 1 bias+gelu; 2 bias+res; 3 bias+lrelu; 4 bias+lrelu+2*res
// WF:   write fp32 out;  WBF: write bf16 hi/lo out (cols < ldob)
#define RS 80                      // smem row stride bytes (32 bf16 + pad)
#define STAGE_SZ 40960             // AH 10240 | AL 10240 | BH 10240 | BL 10240
#define SMEM_TOTAL (2 * STAGE_SZ)

template<int MODE, int EPI, int WF, int WBF>
__global__ void __launch_bounds__(256, 1) mm_k(
    const __nv_bfloat16* __restrict__ AH0, const __nv_bfloat16* __restrict__ AL0,
    const __nv_bfloat16* __restrict__ AH1, const __nv_bfloat16* __restrict__ AL1,
    int ldA,
    const __nv_bfloat16* __restrict__ WH, const __nv_bfloat16* __restrict__ WL,
    int Kw,
    const float* __restrict__ bias,
    const float* __restrict__ res, int ldRes,
    float* __restrict__ out, int ldo,
    __nv_bfloat16* __restrict__ obH, __nv_bfloat16* __restrict__ obL, int ldob)
{
    extern __shared__ char sm[];
    const uint32_t sb = smem_u32(sm);
    const int tid = threadIdx.x;
    const int wid = tid >> 5;
    const int lane = tid & 31;
    const int nc = Kw >> 5;

    int m0 = 0, n0 = 0, bB = 0, gh0 = 0, gw0 = 0;
    if (MODE == 2) {
        bB  = blockIdx.x >> 9;
        gh0 = ((blockIdx.x >> 4) & 31) * 8;
        gw0 = (blockIdx.x & 15) * 16;
    } else {
        m0 = blockIdx.x * 128;
        n0 = blockIdx.y * 128;
    }

    // loader mapping: 2 threads per row, each covers a 32B k-half (2x16B)
    const int lr = tid >> 1;
    const int lh = tid & 1;
    int lph = 0, lpw = 0;
    if (MODE == 2) { lph = gh0 + (lr >> 4); lpw = gw0 + (lr & 15); }

    auto issue_chunk = [&](int cc) {
        const int s = cc & 1;
        const uint32_t base = sb + s * STAGE_SZ;
        const int kin = cc * 32;
        // ---- A ----
        const __nv_bfloat16 *ah, *al;
        uint32_t asz = 16;
        if (MODE == 0) {
            ah = AH0 + (size_t)(m0 + lr) * ldA + kin;
            al = AL0 + (size_t)(m0 + lr) * ldA + kin;
        } else if (MODE == 1) {
            if (kin < 128) {
                ah = AH0 + (size_t)(m0 + lr) * 128 + kin;
                al = AL0 + (size_t)(m0 + lr) * 128 + kin;
            } else {
                ah = AH1 + (size_t)(m0 + lr) * 128 + (kin - 128);
                al = AL1 + (size_t)(m0 + lr) * 128 + (kin - 128);
            }
        } else {
            const int tap = cc >> 2, kk = (cc & 3) * 32;
            const int ih = lph + tap / 3 - 1, iw = lpw + tap % 3 - 1;
            const bool ok = ((unsigned)ih < 256u) && ((unsigned)iw < 256u);
            const size_t pix = ok ? (size_t)((bB * 256 + ih) * 256 + iw) : 0;
            ah = AH0 + pix * 128 + kk;
            al = AL0 + pix * 128 + kk;
            asz = ok ? 16u : 0u;
        }
        const uint32_t da = base + (uint32_t)lr * RS + lh * 32;
        CP_ASYNC(da,              (const char*)ah + lh * 32,      asz);
        CP_ASYNC(da + 16,         (const char*)ah + lh * 32 + 16, asz);
        CP_ASYNC(da + 10240,      (const char*)al + lh * 32,      asz);
        CP_ASYNC(da + 10240 + 16, (const char*)al + lh * 32 + 16, asz);
        // ---- B (weights, K-major rows) ----
        const __nv_bfloat16* bh = WH + (size_t)(n0 + lr) * Kw + kin;
        const __nv_bfloat16* bl = WL + (size_t)(n0 + lr) * Kw + kin;
        const uint32_t db = base + 20480 + (uint32_t)lr * RS + lh * 32;
        CP_ASYNC(db,              (const char*)bh + lh * 32,      16);
        CP_ASYNC(db + 16,         (const char*)bh + lh * 32 + 16, 16);
        CP_ASYNC(db + 10240,      (const char*)bl + lh * 32,      16);
        CP_ASYNC(db + 10240 + 16, (const char*)bl + lh * 32 + 16, 16);
    };

    // warp tiling: warp_m in {0,1} (64 rows), warp_n in {0..3} (32 cols)
    const int wm = (wid & 1) * 64;
    const int wn = (wid >> 1) * 32;
    const uint32_t a_lo = (uint32_t)(lane & 15) * RS + (uint32_t)(lane >> 4) * 16;
    const uint32_t b_lo = (uint32_t)((lane & 7) + ((lane >> 4) << 3)) * RS
                        + (uint32_t)((lane >> 3) & 1) * 16;

    float acc[4][4][4] = {};

    issue_chunk(0);
    CP_COMMIT();

    for (int c = 0; c < nc; c++) {
        if (c + 1 < nc) { issue_chunk(c + 1); CP_COMMIT(); CP_WAIT(1); }
        else            { CP_WAIT(0); }
        __syncthreads();

        const uint32_t base = sb + (c & 1) * STAGE_SZ;
        #pragma unroll
        for (int ks = 0; ks < 2; ks++) {
            uint32_t aH[4][4], aL[4][4], bH[2][4], bL[2][4];
            #pragma unroll
            for (int mi = 0; mi < 4; mi++) {
                const uint32_t ad = base + (uint32_t)(wm + mi * 16) * RS + ks * 32 + a_lo;
                LDM4(aH[mi], ad);
                LDM4(aL[mi], ad + 10240);
            }
            #pragma unroll
            for (int bg = 0; bg < 2; bg++) {
                const uint32_t bd = base + 20480 + (uint32_t)(wn + bg * 16) * RS + ks * 32 + b_lo;
                LDM4(bH[bg], bd);
                LDM4(bL[bg], bd + 10240);
            }
            #pragma unroll
            for (int mi = 0; mi < 4; mi++)
                #pragma unroll
                for (int nj = 0; nj < 4; nj++) {
                    const uint32_t* ph = &bH[nj >> 1][(nj & 1) * 2];
                    const uint32_t* pl = &bL[nj >> 1][(nj & 1) * 2];
                    MMA(acc[mi][nj], aH[mi], ph[0], ph[1]);
                    MMA(acc[mi][nj], aH[mi], pl[0], pl[1]);
                    MMA(acc[mi][nj], aL[mi], ph[0], ph[1]);
                }
        }
        __syncthreads();
    }

    // ---- epilogue ----
    #pragma unroll
    for (int mi = 0; mi < 4; mi++) {
        #pragma unroll
        for (int h2 = 0; h2 < 2; h2++) {
            const int r = wm + mi * 16 + (lane >> 2) + h2 * 8;
            size_t orow;
            if (MODE == 2)
                orow = (size_t)((bB * 256 + gh0 + (r >> 4)) * 256 + gw0 + (r & 15));
            else
                orow = (size_t)(m0 + r);
            #pragma unroll
            for (int nj = 0; nj < 4; nj++) {
                const int n = n0 + wn + nj * 8 + (lane & 3) * 2;
                float v0 = acc[mi][nj][h2 * 2 + 0] + __ldg(&bias[n]);
                float v1 = acc[mi][nj][h2 * 2 + 1] + __ldg(&bias[n + 1]);
                if (EPI == 1) {
                    v0 = 0.5f * v0 * (1.0f + erff(v0 * 0.7071067811865476f));
                    v1 = 0.5f * v1 * (1.0f + erff(v1 * 0.7071067811865476f));
                }
                if (EPI == 3 || EPI == 4) {
                    v0 = v0 >= 0.f ? v0 : 0.01f * v0;
                    v1 = v1 >= 0.f ? v1 : 0.01f * v1;
                }
                if (EPI == 2) {
                    const float2 rv = *(const float2*)(res + orow * ldRes + n);
                    v0 += rv.x; v1 += rv.y;
                }
                if (EPI == 4) {
                    const float2 rv = *(const float2*)(res + orow * ldRes + n);
                    v0 += 2.f * rv.x; v1 += 2.f * rv.y;
                }
                if (WF)
                    *(float2*)(out + orow * ldo + n) = make_float2(v0, v1);
                if (WBF && n < ldob) {
                    float h0 = __bfloat162float(__float2bfloat16(v0));
                    float h1 = __bfloat162float(__float2bfloat16(v1));
                    *(uint32_t*)(obH + orow * ldob + n) = pack_bf2(v0, v1);
                    *(uint32_t*)(obL + orow * ldob + n) = pack_bf2(v0 - h0, v1 - h1);
                }
            }
        }
    }
}

// ---------------- LayerNorm (fp32 in, bf16 hi/lo out) ----------------
__global__ void __launch_bounds__(256) ln_k(
    const float* __restrict__ in, int stride,
    const float* __restrict__ g, const float* __restrict__ bta,
    __nv_bfloat16* __restrict__ oh, __nv_bfloat16* __restrict__ ol)
{
    const int token = blockIdx.x * 8 + (threadIdx.x >> 5);
    const int lane = threadIdx.x & 31;
    const float* p = in + (size_t)token * stride;
    float4 v = *(const float4*)(p + lane * 4);
    float s  = v.x + v.y + v.z + v.w;
    float sq = v.x * v.x + v.y * v.y + v.z * v.z + v.w * v.w;
    #pragma unroll
    for (int o = 16; o; o >>= 1) {
        s  += __shfl_xor_sync(0xffffffffu, s,  o);
        sq += __shfl_xor_sync(0xffffffffu, sq, o);
    }
    const float mu  = s * (1.0f / 128.0f);
    const float var = sq * (1.0f / 128.0f) - mu * mu;
    const float rs  = rsqrtf(var + 1e-5f);
    float4 gv = *(const float4*)(g + lane * 4);
    float4 bv = *(const float4*)(bta + lane * 4);
    float o0 = (v.x - mu) * rs * gv.x + bv.x;
    float o1 = (v.y - mu) * rs * gv.y + bv.y;
    float o2 = (v.z - mu) * rs * gv.z + bv.z;
    float o3 = (v.w - mu) * rs * gv.w + bv.w;
    float h0 = __bfloat162float(__float2bfloat16(o0));
    float h1 = __bfloat162float(__float2bfloat16(o1));
    float h2 = __bfloat162float(__float2bfloat16(o2));
    float h3 = __bfloat162float(__float2bfloat16(o3));
    const size_t off = (size_t)token * 128 + lane * 4;
    *(uint2*)(oh + off) = make_uint2(pack_bf2(o0, o1), pack_bf2(o2, o3));
    *(uint2*)(ol + off) = make_uint2(pack_bf2(o0 - h0, o1 - h1), pack_bf2(o2 - h2, o3 - h3));
}

// ---------------- windowed attention (fp32; bf16 hi/lo out) ----------------
__global__ void __launch_bounds__(256) attn_k(
    const float* __restrict__ qkv, const float* __restrict__ rpb,
    __nv_bfloat16* __restrict__ oh, __nv_bfloat16* __restrict__ ol)
{
    __shared__ float qs[64][32];
    __shared__ float ks[64][33];
    __shared__ float vs[64][33];
    __shared__ float Ps[64][65];
    __shared__ int pixS[64];
    __shared__ int ridS[64];

    const int tid = threadIdx.x;
    const int head = blockIdx.x & 3;
    const int w = (blockIdx.x >> 2) & 1023;
    const int b = blockIdx.x >> 12;
    const int wi = w >> 5, wj = w & 31;

    if (tid < 64) {
        const int ti = tid >> 3, tj = tid & 7;
        const int hh = wi * 8 + ti, ww = wj * 8 + tj;
        pixS[tid] = (b * 256 + ((hh + 4) & 255)) * 256 + ((ww + 4) & 255);
        const int rh = hh < 248 ? 0 : (hh < 252 ? 1 : 2);
        const int rw = ww < 248 ? 0 : (ww < 252 ? 1 : 2);
        ridS[tid] = rh * 3 + rw;
    }
    __syncthreads();

    const int ho = head * 32;
    for (int idx = tid; idx < 2048; idx += 256) {
        const int t = idx >> 5, d = idx & 31;
        const size_t base = (size_t)pixS[t] * 384 + ho + d;
        qs[t][d] = qkv[base];
        ks[t][d] = qkv[base + 128];
        vs[t][d] = qkv[base + 256];
    }
    __syncthreads();

    const int warp = tid >> 5, lane = tid & 31;
    #pragma unroll
    for (int rr = 0; rr < 8; rr++) {
        const int r = warp * 8 + rr;
        float s0 = 0.f, s1 = 0.f;
        #pragma unroll
        for (int d = 0; d < 32; d++) {
            const float qv = qs[r][d];
            s0 += qv * ks[lane][d];
            s1 += qv * ks[lane + 32][d];
        }
        const int ri = r >> 3, rj = r & 7;
        const int rid_r = ridS[r];
        {
            const int c = lane;
            const int rel = (ri - (c >> 3) + 7) * 15 + (rj - (c & 7) + 7);
            s0 = s0 * 0.17677669529663687f + rpb[rel * 4 + head];
            if (rid_r != ridS[c]) s0 -= 1e9f;
        }
        {
            const int c = lane + 32;
            const int rel = (ri - (c >> 3) + 7) * 15 + (rj - (c & 7) + 7);
            s1 = s1 * 0.17677669529663687f + rpb[rel * 4 + head];
            if (rid_r != ridS[c]) s1 -= 1e9f;
        }
        float mx = fmaxf(s0, s1);
        #pragma unroll
        for (int o = 16; o; o >>= 1) mx = fmaxf(mx, __shfl_xor_sync(0xffffffffu, mx, o));
        float e0 = expf(s0 - mx), e1 = expf(s1 - mx);
        float sm = e0 + e1;
        #pragma unroll
        for (int o = 16; o; o >>= 1) sm += __shfl_xor_sync(0xffffffffu, sm, o);
        const float inv = 1.0f / sm;
        Ps[r][lane] = e0 * inv;
        Ps[r][lane + 32] = e1 * inv;
    }
    __syncthreads();

    const int i = tid >> 2, d0 = (tid & 3) * 8;
    float acc[8] = {};
    #pragma unroll
    for (int j = 0; j < 64; j++) {
        const float p = Ps[i][j];
        #pragma unroll
        for (int dd = 0; dd < 8; dd++) acc[dd] += p * vs[j][d0 + dd];
    }
    const size_t ob = (size_t)pixS[i] * 128 + ho + d0;
    #pragma unroll
    for (int dd = 0; dd < 8; dd += 2) {
        float h0 = __bfloat162float(__float2bfloat16(acc[dd]));
        float h1 = __bfloat162float(__float2bfloat16(acc[dd + 1]));
        *(uint32_t*)(oh + ob + dd) = pack_bf2(acc[dd], acc[dd + 1]);
        *(uint32_t*)(ol + ob + dd) = pack_bf2(acc[dd] - h0, acc[dd + 1] - h1);
    }
}

// ===========================================================================
extern "C" void kernel_launch(void* const* d_in, const int* in_sizes, int n_in,
                              void* d_out, int out_size)
{
    const float* x    = (const float*)d_in[0];
    const float* c1w  = (const float*)d_in[1];
    const float* c1b  = (const float*)d_in[2];
    const float* rw1  = (const float*)d_in[3];
    const float* rb1  = (const float*)d_in[4];
    const float* rw2  = (const float*)d_in[5];
    const float* rb2  = (const float*)d_in[6];
    const float* ln1g = (const float*)d_in[7];
    const float* ln1b = (const float*)d_in[8];
    const float* qkvw = (const float*)d_in[9];
    const float* qkvb = (const float*)d_in[10];
    const float* rpb  = (const float*)d_in[11];
    const float* pw   = (const float*)d_in[12];
    const float* pb   = (const float*)d_in[13];
    const float* ln2g = (const float*)d_in[14];
    const float* ln2b = (const float*)d_in[15];
    const float* mw1  = (const float*)d_in[16];
    const float* mb1  = (const float*)d_in[17];
    const float* mw2  = (const float*)d_in[18];
    const float* mb2  = (const float*)d_in[19];
    const float* c2w  = (const float*)d_in[20];
    const float* c2b  = (const float*)d_in[21];
    float* out = (float*)d_out;

    float *y, *qkv, *t;
    __nv_bfloat16 *xh,*xl,*yh,*yl,*rh,*rl,*ch,*cl,*lh,*ll,*ah,*al,*uh,*ul,*th,*tl,*wth,*wtl;
    cudaGetSymbolAddress((void**)&y,   g_y);
    cudaGetSymbolAddress((void**)&qkv, g_qkv);
    cudaGetSymbolAddress((void**)&t,   g_t);
    cudaGetSymbolAddress((void**)&xh, g_xh); cudaGetSymbolAddress((void**)&xl, g_xl);
    cudaGetSymbolAddress((void**)&yh, g_yh); cudaGetSymbolAddress((void**)&yl, g_yl);
    cudaGetSymbolAddress((void**)&rh, g_rh); cudaGetSymbolAddress((void**)&rl, g_rl);
    cudaGetSymbolAddress((void**)&ch, g_ch); cudaGetSymbolAddress((void**)&cl, g_cl);
    cudaGetSymbolAddress((void**)&lh, g_lh); cudaGetSymbolAddress((void**)&ll, g_ll);
    cudaGetSymbolAddress((void**)&ah, g_ah); cudaGetSymbolAddress((void**)&al, g_al);
    cudaGetSymbolAddress((void**)&uh, g_uh); cudaGetSymbolAddress((void**)&ul, g_ul);
    cudaGetSymbolAddress((void**)&th, g_th); cudaGetSymbolAddress((void**)&tl, g_tl);
    cudaGetSymbolAddress((void**)&wth, g_wth); cudaGetSymbolAddress((void**)&wtl, g_wtl);

    cudaFuncSetAttribute(mm_k<0,0,1,1>, cudaFuncAttributeMaxDynamicSharedMemorySize, SMEM_TOTAL);
    cudaFuncSetAttribute(mm_k<2,3,0,1>, cudaFuncAttributeMaxDynamicSharedMemorySize, SMEM_TOTAL);
    cudaFuncSetAttribute(mm_k<2,4,0,1>, cudaFuncAttributeMaxDynamicSharedMemorySize, SMEM_TOTAL);
    cudaFuncSetAttribute(mm_k<0,0,1,0>, cudaFuncAttributeMaxDynamicSharedMemorySize, SMEM_TOTAL);
    cudaFuncSetAttribute(mm_k<0,2,1,0>, cudaFuncAttributeMaxDynamicSharedMemorySize, SMEM_TOTAL);
    cudaFuncSetAttribute(mm_k<0,1,0,1>, cudaFuncAttributeMaxDynamicSharedMemorySize, SMEM_TOTAL);
    cudaFuncSetAttribute(mm_k<0,2,0,1>, cudaFuncAttributeMaxDynamicSharedMemorySize, SMEM_TOTAL);
    cudaFuncSetAttribute(mm_k<1,2,1,0>, cudaFuncAttributeMaxDynamicSharedMemorySize, SMEM_TOTAL);

    // 0a. weight prep
    PrepArgs pa;
    pa.src[0]=c1w; pa.K[0]=256;  pa.N[0]=256; pa.off[0]=OFF_C1;
    pa.src[1]=rw1; pa.K[1]=1152; pa.N[1]=128; pa.off[1]=OFF_RW1;
    pa.src[2]=rw2; pa.K[2]=1152; pa.N[2]=128; pa.off[2]=OFF_RW2;
    pa.src[3]=qkvw;pa.K[3]=128;  pa.N[3]=384; pa.off[3]=OFF_QKV;
    pa.src[4]=pw;  pa.K[4]=128;  pa.N[4]=128; pa.off[4]=OFF_PW;
    pa.src[5]=mw1; pa.K[5]=128;  pa.N[5]=512; pa.off[5]=OFF_MW1;
    pa.src[6]=mw2; pa.K[6]=512;  pa.N[6]=128; pa.off[6]=OFF_MW2;
    pa.src[7]=c2w; pa.K[7]=256;  pa.N[7]=256; pa.off[7]=OFF_C2;
    prep_k<<<dim3(576, 8), 256>>>(pa, wth, wtl);
    // 0b. convert x
    cvt_k<<<32768, 256>>>(x, xh, xl, M_TOK * 64);

    const int M = M_TOK;
    // 1. conv1x1 #1: y(fp32 [M,256]) + ybf(cols 0-127)
    mm_k<0,0,1,1><<<dim3(M/128, 2), 256, SMEM_TOTAL>>>(
        xh, xl, nullptr, nullptr, 256, wth+OFF_C1, wtl+OFF_C1, 256,
        c1b, nullptr, 0, y, 256, yh, yl, 128);
    // 2. conv3x3 #1 + lrelu -> rbf
    mm_k<2,3,0,1><<<1024, 256, SMEM_TOTAL>>>(
        yh, yl, nullptr, nullptr, 128, wth+OFF_RW1, wtl+OFF_RW1, 1152,
        rb1, nullptr, 0, nullptr, 0, rh, rl, 128);
    // 3. conv3x3 #2 + lrelu + 2*conv_x -> cxbf
    mm_k<2,4,0,1><<<1024, 256, SMEM_TOTAL>>>(
        rh, rl, nullptr, nullptr, 128, wth+OFF_RW2, wtl+OFF_RW2, 1152,
        rb2, y, 256, nullptr, 0, ch, cl, 128);
    // 4. LN1 on trans_x -> lnbf
    ln_k<<<M/8, 256>>>(y + 128, 256, ln1g, ln1b, lh, ll);
    // 5. qkv (fp32)
    mm_k<0,0,1,0><<<dim3(M/128, 3), 256, SMEM_TOTAL>>>(
        lh, ll, nullptr, nullptr, 128, wth+OFF_QKV, wtl+OFF_QKV, 128,
        qkvb, nullptr, 0, qkv, 384, nullptr, nullptr, 0);
    // 6. attention -> attbf
    attn_k<<<8192, 256>>>(qkv, rpb, ah, al);
    // 7. proj + residual(trans_x) -> t (fp32)
    mm_k<0,2,1,0><<<dim3(M/128, 1), 256, SMEM_TOTAL>>>(
        ah, al, nullptr, nullptr, 128, wth+OFF_PW, wtl+OFF_PW, 128,
        pb, y + 128, 256, t, 128, nullptr, nullptr, 0);
    // 8. LN2 -> lnbf
    ln_k<<<M/8, 256>>>(t, 128, ln2g, ln2b, lh, ll);
    // 9. mlp1 + gelu -> ubf
    mm_k<0,1,0,1><<<dim3(M/128, 4), 256, SMEM_TOTAL>>>(
        lh, ll, nullptr, nullptr, 128, wth+OFF_MW1, wtl+OFF_MW1, 128,
        mb1, nullptr, 0, nullptr, 0, uh, ul, 512);
    // 10. mlp2 + residual(t) -> t2bf
    mm_k<0,2,0,1><<<dim3(M/128, 1), 256, SMEM_TOTAL>>>(
        uh, ul, nullptr, nullptr, 512, wth+OFF_MW2, wtl+OFF_MW2, 512,
        mb2, t, 128, nullptr, 0, th, tl, 128);
    // 11. conv1x1 #2 on concat(cx,t2) + x -> out
    mm_k<1,2,1,0><<<dim3(M/128, 2), 256, SMEM_TOTAL>>>(
        ch, cl, th, tl, 0, wth+OFF_C2, wtl+OFF_C2, 256,
        c2b, x, 256, out, 256, nullptr, nullptr, 0);
}

// round 6
// speedup vs baseline: 2.1836x; 1.0024x over previous
#include <cuda_runtime.h>
#include <cuda_bf16.h>
#include <math.h>
#include <stdint.h>

// ===========================================================================
// ConvTransBlock via legacy tensor-core path (mma.sync bf16, hi/lo split).
// B=2, H=W=256, C=256 (CD=128 | TD=128), WS=8, NH=4, HD=32.
// R4: break accumulator RAW chains (split-product as outer loop).
// ===========================================================================

#define M_TOK 131072

// ---------------- fp32 buffers ----------------
__device__ float g_y  [131072 * 256];   // conv1 out
__device__ float g_qkv[131072 * 384];
__device__ float g_t  [131072 * 128];   // trans after proj residual

// ---------------- bf16 hi/lo activation buffers ----------------
__device__ __nv_bfloat16 g_xh[131072*256], g_xl[131072*256];
__device__ __nv_bfloat16 g_yh[131072*128], g_yl[131072*128];   // conv half of y
__device__ __nv_bfloat16 g_rh[131072*128], g_rl[131072*128];
__device__ __nv_bfloat16 g_ch[131072*128], g_cl[131072*128];   // cx
__device__ __nv_bfloat16 g_lh[131072*128], g_ll[131072*128];   // ln out
__device__ __nv_bfloat16 g_ah[131072*128], g_al[131072*128];   // attn out
__device__ __nv_bfloat16 g_uh[131072*512], g_ul[131072*512];   // mlp hidden
__device__ __nv_bfloat16 g_th[131072*128], g_tl[131072*128];   // t2

// transposed bf16 weights (hi / lo), K-major rows per n
#define WT_TOTAL 622592
__device__ __align__(256) __nv_bfloat16 g_wth[WT_TOTAL];
__device__ __align__(256) __nv_bfloat16 g_wtl[WT_TOTAL];
#define OFF_C1   0
#define OFF_RW1  65536
#define OFF_RW2  212992
#define OFF_QKV  360448
#define OFF_PW   409600
#define OFF_MW1  425984
#define OFF_MW2  491520
#define OFF_C2   557056

// ---------------- PTX helpers (all sm_80-compatible) ----------------
__device__ __forceinline__ uint32_t smem_u32(const void* p) {
    uint32_t a;
    asm("{ .reg .u64 t; cvta.to.shared.u64 t, %1; cvt.u32.u64 %0, t; }" : "=r"(a) : "l"(p));
    return a;
}
#define CP_ASYNC(dst, src, sz) \
    asm volatile("cp.async.cg.shared.global [%0], [%1], 16, %2;" \
        :: "r"(dst), "l"(src), "r"(sz))
#define CP_COMMIT() asm volatile("cp.async.commit_group;")
#define CP_WAIT(n)  asm volatile("cp.async.wait_group %0;" :: "n"(n))
#define LDM4(r, addr) \
    asm volatile("ldmatrix.sync.aligned.m8n8.x4.shared.b16 {%0,%1,%2,%3}, [%4];" \
        : "=r"((r)[0]), "=r"((r)[1]), "=r"((r)[2]), "=r"((r)[3]) : "r"(addr))
#define MMA(d, a, b0, b1) \
    asm volatile("mma.sync.aligned.m16n8k16.row.col.f32.bf16.bf16.f32 " \
        "{%0,%1,%2,%3}, {%4,%5,%6,%7}, {%8,%9}, {%0,%1,%2,%3};" \
        : "+f"((d)[0]), "+f"((d)[1]), "+f"((d)[2]), "+f"((d)[3]) \
        : "r"((a)[0]), "r"((a)[1]), "r"((a)[2]), "r"((a)[3]), "r"(b0), "r"(b1))

__device__ __forceinline__ uint32_t pack_bf2(float a, float b) {
    __nv_bfloat16 ha = __float2bfloat16(a), hb = __float2bfloat16(b);
    return ((uint32_t)__bfloat16_as_ushort(hb) << 16) | (uint32_t)__bfloat16_as_ushort(ha);
}

// ---------------- weight prep: W[k][n] -> Wt[n][k] bf16 hi/lo ----------------
struct PrepArgs { const float* src[8]; int K[8], N[8], off[8]; };
__global__ void __launch_bounds__(256) prep_k(PrepArgs a,
    __nv_bfloat16* __restrict__ dh, __nv_bfloat16* __restrict__ dl)
{
    int w = blockIdx.y;
    int K = a.K[w], N = a.N[w];
    int idx = blockIdx.x * 256 + threadIdx.x;
    if (idx >= K * N) return;
    int n = idx / K, k = idx - n * K;
    float v = a.src[w][(size_t)k * N + n];
    __nv_bfloat16 h = __float2bfloat16(v);
    dh[a.off[w] + idx] = h;
    dl[a.off[w] + idx] = __float2bfloat16(v - __bfloat162float(h));
}

// ---------------- fp32 -> bf16 hi/lo converter (for x) ----------------
__global__ void __launch_bounds__(256) cvt_k(const float* __restrict__ in,
    __nv_bfloat16* __restrict__ oh, __nv_bfloat16* __restrict__ ol, int n4)
{
    int i = blockIdx.x * 256 + threadIdx.x;
    if (i >= n4) return;
    float4 v = ((const float4*)in)[i];
    float h0 = __bfloat162float(__float2bfloat16(v.x));
    float h1 = __bfloat162float(__float2bfloat16(v.y));
    float h2 = __bfloat162float(__float2bfloat16(v.z));
    float h3 = __bfloat162float(__float2bfloat16(v.w));
    uint2 H = make_uint2(pack_bf2(v.x, v.y), pack_bf2(v.z, v.w));
    uint2 L = make_uint2(pack_bf2(v.x - h0, v.y - h1), pack_bf2(v.z - h2, v.w - h3));
    ((uint2*)oh)[i] = H;
    ((uint2*)ol)[i] = L;
}

// ---------------- unified tensor-core GEMM / implicit-GEMM conv ----------------
// MODE: 0 gemm, 1 concat(A0bf,A1bf) along K, 2 conv3x3 (A = [M,128] bf16, halo)
// EPI:  0 bias; 1 bias+gelu; 2 bias+res; 3 bias+lrelu; 4 bias+lrelu+2*res
// WF:   write fp32 out;  WBF: write bf16 hi/lo out (cols < ldob)
#define RS 80                      // smem row stride bytes (32 bf16 + pad)
#define STAGE_SZ 40960             // AH 10240 | AL 10240 | BH 10240 | BL 10240
#define SMEM_TOTAL (2 * STAGE_SZ)

template<int MODE, int EPI, int WF, int WBF>
__global__ void __launch_bounds__(256, 1) mm_k(
    const __nv_bfloat16* __restrict__ AH0, const __nv_bfloat16* __restrict__ AL0,
    const __nv_bfloat16* __restrict__ AH1, const __nv_bfloat16* __restrict__ AL1,
    int ldA,
    const __nv_bfloat16* __restrict__ WH, const __nv_bfloat16* __restrict__ WL,
    int Kw,
    const float* __restrict__ bias,
    const float* __restrict__ res, int ldRes,
    float* __restrict__ out, int ldo,
    __nv_bfloat16* __restrict__ obH, __nv_bfloat16* __restrict__ obL, int ldob)
{
    extern __shared__ char sm[];
    const uint32_t sb = smem_u32(sm);
    const int tid = threadIdx.x;
    const int wid = tid >> 5;
    const int lane = tid & 31;
    const int nc = Kw >> 5;

    int m0 = 0, n0 = 0, bB = 0, gh0 = 0, gw0 = 0;
    if (MODE == 2) {
        bB  = blockIdx.x >> 9;
        gh0 = ((blockIdx.x >> 4) & 31) * 8;
        gw0 = (blockIdx.x & 15) * 16;
    } else {
        m0 = blockIdx.x * 128;
        n0 = blockIdx.y * 128;
    }

    // loader mapping: 2 threads per row, each covers a 32B k-half (2x16B)
    const int lr = tid >> 1;
    const int lh = tid & 1;
    int lph = 0, lpw = 0;
    if (MODE == 2) { lph = gh0 + (lr >> 4); lpw = gw0 + (lr & 15); }

    auto issue_chunk = [&](int cc) {
        const int s = cc & 1;
        const uint32_t base = sb + s * STAGE_SZ;
        const int kin = cc * 32;
        // ---- A ----
        const __nv_bfloat16 *ah, *al;
        uint32_t asz = 16;
        if (MODE == 0) {
            ah = AH0 + (size_t)(m0 + lr) * ldA + kin;
            al = AL0 + (size_t)(m0 + lr) * ldA + kin;
        } else if (MODE == 1) {
            if (kin < 128) {
                ah = AH0 + (size_t)(m0 + lr) * 128 + kin;
                al = AL0 + (size_t)(m0 + lr) * 128 + kin;
            } else {
                ah = AH1 + (size_t)(m0 + lr) * 128 + (kin - 128);
                al = AL1 + (size_t)(m0 + lr) * 128 + (kin - 128);
            }
        } else {
            const int tap = cc >> 2, kk = (cc & 3) * 32;
            const int ih = lph + tap / 3 - 1, iw = lpw + tap % 3 - 1;
            const bool ok = ((unsigned)ih < 256u) && ((unsigned)iw < 256u);
            const size_t pix = ok ? (size_t)((bB * 256 + ih) * 256 + iw) : 0;
            ah = AH0 + pix * 128 + kk;
            al = AL0 + pix * 128 + kk;
            asz = ok ? 16u : 0u;
        }
        const uint32_t da = base + (uint32_t)lr * RS + lh * 32;
        CP_ASYNC(da,              (const char*)ah + lh * 32,      asz);
        CP_ASYNC(da + 16,         (const char*)ah + lh * 32 + 16, asz);
        CP_ASYNC(da + 10240,      (const char*)al + lh * 32,      asz);
        CP_ASYNC(da + 10240 + 16, (const char*)al + lh * 32 + 16, asz);
        // ---- B (weights, K-major rows) ----
        const __nv_bfloat16* bh = WH + (size_t)(n0 + lr) * Kw + kin;
        const __nv_bfloat16* bl = WL + (size_t)(n0 + lr) * Kw + kin;
        const uint32_t db = base + 20480 + (uint32_t)lr * RS + lh * 32;
        CP_ASYNC(db,              (const char*)bh + lh * 32,      16);
        CP_ASYNC(db + 16,         (const char*)bh + lh * 32 + 16, 16);
        CP_ASYNC(db + 10240,      (const char*)bl + lh * 32,      16);
        CP_ASYNC(db + 10240 + 16, (const char*)bl + lh * 32 + 16, 16);
    };

    // warp tiling: warp_m in {0,1} (64 rows), warp_n in {0..3} (32 cols)
    const int wm = (wid & 1) * 64;
    const int wn = (wid >> 1) * 32;
    const uint32_t a_lo = (uint32_t)(lane & 15) * RS + (uint32_t)(lane >> 4) * 16;
    const uint32_t b_lo = (uint32_t)((lane & 7) + ((lane >> 4) << 3)) * RS
                        + (uint32_t)((lane >> 3) & 1) * 16;

    float acc[4][4][4] = {};

    issue_chunk(0);
    CP_COMMIT();

    for (int c = 0; c < nc; c++) {
        if (c + 1 < nc) { issue_chunk(c + 1); CP_COMMIT(); CP_WAIT(1); }
        else            { CP_WAIT(0); }
        __syncthreads();

        const uint32_t base = sb + (c & 1) * STAGE_SZ;
        #pragma unroll
        for (int ks = 0; ks < 2; ks++) {
            uint32_t aH[4][4], aL[4][4], bH[2][4], bL[2][4];
            #pragma unroll
            for (int mi = 0; mi < 4; mi++) {
                const uint32_t ad = base + (uint32_t)(wm + mi * 16) * RS + ks * 32 + a_lo;
                LDM4(aH[mi], ad);
                LDM4(aL[mi], ad + 10240);
            }
            #pragma unroll
            for (int bg = 0; bg < 2; bg++) {
                const uint32_t bd = base + 20480 + (uint32_t)(wn + bg * 16) * RS + ks * 32 + b_lo;
                LDM4(bH[bg], bd);
                LDM4(bL[bg], bd + 10240);
            }
            // Split product as OUTER loop: same-accumulator MMAs are 16
            // independent MMAs apart -> no RAW serialization on the HMMA pipe.
            #pragma unroll
            for (int s = 0; s < 3; s++) {
                #pragma unroll
                for (int mi = 0; mi < 4; mi++) {
                    const uint32_t* af = (s == 2) ? aL[mi] : aH[mi];
                    #pragma unroll
                    for (int nj = 0; nj < 4; nj++) {
                        const uint32_t* bf = (s == 1) ? &bL[nj >> 1][(nj & 1) * 2]
                                                      : &bH[nj >> 1][(nj & 1) * 2];
                        MMA(acc[mi][nj], af, bf[0], bf[1]);
                    }
                }
            }
        }
        __syncthreads();
    }

    // ---- epilogue ----
    #pragma unroll
    for (int mi = 0; mi < 4; mi++) {
        #pragma unroll
        for (int h2 = 0; h2 < 2; h2++) {
            const int r = wm + mi * 16 + (lane >> 2) + h2 * 8;
            size_t orow;
            if (MODE == 2)
                orow = (size_t)((bB * 256 + gh0 + (r >> 4)) * 256 + gw0 + (r & 15));
            else
                orow = (size_t)(m0 + r);
            #pragma unroll
            for (int nj = 0; nj < 4; nj++) {
                const int n = n0 + wn + nj * 8 + (lane & 3) * 2;
                float v0 = acc[mi][nj][h2 * 2 + 0] + __ldg(&bias[n]);
                float v1 = acc[mi][nj][h2 * 2 + 1] + __ldg(&bias[n + 1]);
                if (EPI == 1) {
                    v0 = 0.5f * v0 * (1.0f + erff(v0 * 0.7071067811865476f));
                    v1 = 0.5f * v1 * (1.0f + erff(v1 * 0.7071067811865476f));
                }
                if (EPI == 3 || EPI == 4) {
                    v0 = v0 >= 0.f ? v0 : 0.01f * v0;
                    v1 = v1 >= 0.f ? v1 : 0.01f * v1;
                }
                if (EPI == 2) {
                    const float2 rv = *(const float2*)(res + orow * ldRes + n);
                    v0 += rv.x; v1 += rv.y;
                }
                if (EPI == 4) {
                    const float2 rv = *(const float2*)(res + orow * ldRes + n);
                    v0 += 2.f * rv.x; v1 += 2.f * rv.y;
                }
                if (WF)
                    *(float2*)(out + orow * ldo + n) = make_float2(v0, v1);
                if (WBF && n < ldob) {
                    float h0 = __bfloat162float(__float2bfloat16(v0));
                    float h1 = __bfloat162float(__float2bfloat16(v1));
                    *(uint32_t*)(obH + orow * ldob + n) = pack_bf2(v0, v1);
                    *(uint32_t*)(obL + orow * ldob + n) = pack_bf2(v0 - h0, v1 - h1);
                }
            }
        }
    }
}

// ---------------- LayerNorm (fp32 in, bf16 hi/lo out) ----------------
__global__ void __launch_bounds__(256) ln_k(
    const float* __restrict__ in, int stride,
    const float* __restrict__ g, const float* __restrict__ bta,
    __nv_bfloat16* __restrict__ oh, __nv_bfloat16* __restrict__ ol)
{
    const int token = blockIdx.x * 8 + (threadIdx.x >> 5);
    const int lane = threadIdx.x & 31;
    const float* p = in + (size_t)token * stride;
    float4 v = *(const float4*)(p + lane * 4);
    float s  = v.x + v.y + v.z + v.w;
    float sq = v.x * v.x + v.y * v.y + v.z * v.z + v.w * v.w;
    #pragma unroll
    for (int o = 16; o; o >>= 1) {
        s  += __shfl_xor_sync(0xffffffffu, s,  o);
        sq += __shfl_xor_sync(0xffffffffu, sq, o);
    }
    const float mu  = s * (1.0f / 128.0f);
    const float var = sq * (1.0f / 128.0f) - mu * mu;
    const float rs  = rsqrtf(var + 1e-5f);
    float4 gv = *(const float4*)(g + lane * 4);
    float4 bv = *(const float4*)(bta + lane * 4);
    float o0 = (v.x - mu) * rs * gv.x + bv.x;
    float o1 = (v.y - mu) * rs * gv.y + bv.y;
    float o2 = (v.z - mu) * rs * gv.z + bv.z;
    float o3 = (v.w - mu) * rs * gv.w + bv.w;
    float h0 = __bfloat162float(__float2bfloat16(o0));
    float h1 = __bfloat162float(__float2bfloat16(o1));
    float h2 = __bfloat162float(__float2bfloat16(o2));
    float h3 = __bfloat162float(__float2bfloat16(o3));
    const size_t off = (size_t)token * 128 + lane * 4;
    *(uint2*)(oh + off) = make_uint2(pack_bf2(o0, o1), pack_bf2(o2, o3));
    *(uint2*)(ol + off) = make_uint2(pack_bf2(o0 - h0, o1 - h1), pack_bf2(o2 - h2, o3 - h3));
}

// ---------------- windowed attention (fp32; bf16 hi/lo out) ----------------
__global__ void __launch_bounds__(256) attn_k(
    const float* __restrict__ qkv, const float* __restrict__ rpb,
    __nv_bfloat16* __restrict__ oh, __nv_bfloat16* __restrict__ ol)
{
    __shared__ float qs[64][32];
    __shared__ float ks[64][33];
    __shared__ float vs[64][33];
    __shared__ float Ps[64][65];
    __shared__ int pixS[64];
    __shared__ int ridS[64];

    const int tid = threadIdx.x;
    const int head = blockIdx.x & 3;
    const int w = (blockIdx.x >> 2) & 1023;
    const int b = blockIdx.x >> 12;
    const int wi = w >> 5, wj = w & 31;

    if (tid < 64) {
        const int ti = tid >> 3, tj = tid & 7;
        const int hh = wi * 8 + ti, ww = wj * 8 + tj;
        pixS[tid] = (b * 256 + ((hh + 4) & 255)) * 256 + ((ww + 4) & 255);
        const int rh = hh < 248 ? 0 : (hh < 252 ? 1 : 2);
        const int rw = ww < 248 ? 0 : (ww < 252 ? 1 : 2);
        ridS[tid] = rh * 3 + rw;
    }
    __syncthreads();

    const int ho = head * 32;
    for (int idx = tid; idx < 2048; idx += 256) {
        const int t = idx >> 5, d = idx & 31;
        const size_t base = (size_t)pixS[t] * 384 + ho + d;
        qs[t][d] = qkv[base];
        ks[t][d] = qkv[base + 128];
        vs[t][d] = qkv[base + 256];
    }
    __syncthreads();

    const int warp = tid >> 5, lane = tid & 31;
    #pragma unroll
    for (int rr = 0; rr < 8; rr++) {
        const int r = warp * 8 + rr;
        float s0 = 0.f, s1 = 0.f;
        #pragma unroll
        for (int d = 0; d < 32; d++) {
            const float qv = qs[r][d];
            s0 += qv * ks[lane][d];
            s1 += qv * ks[lane + 32][d];
        }
        const int ri = r >> 3, rj = r & 7;
        const int rid_r = ridS[r];
        {
            const int c = lane;
            const int rel = (ri - (c >> 3) + 7) * 15 + (rj - (c & 7) + 7);
            s0 = s0 * 0.17677669529663687f + rpb[rel * 4 + head];
            if (rid_r != ridS[c]) s0 -= 1e9f;
        }
        {
            const int c = lane + 32;
            const int rel = (ri - (c >> 3) + 7) * 15 + (rj - (c & 7) + 7);
            s1 = s1 * 0.17677669529663687f + rpb[rel * 4 + head];
            if (rid_r != ridS[c]) s1 -= 1e9f;
        }
        float mx = fmaxf(s0, s1);
        #pragma unroll
        for (int o = 16; o; o >>= 1) mx = fmaxf(mx, __shfl_xor_sync(0xffffffffu, mx, o));
        float e0 = expf(s0 - mx), e1 = expf(s1 - mx);
        float sm = e0 + e1;
        #pragma unroll
        for (int o = 16; o; o >>= 1) sm += __shfl_xor_sync(0xffffffffu, sm, o);
        const float inv = 1.0f / sm;
        Ps[r][lane] = e0 * inv;
        Ps[r][lane + 32] = e1 * inv;
    }
    __syncthreads();

    const int i = tid >> 2, d0 = (tid & 3) * 8;
    float acc[8] = {};
    #pragma unroll
    for (int j = 0; j < 64; j++) {
        const float p = Ps[i][j];
        #pragma unroll
        for (int dd = 0; dd < 8; dd++) acc[dd] += p * vs[j][d0 + dd];
    }
    const size_t ob = (size_t)pixS[i] * 128 + ho + d0;
    #pragma unroll
    for (int dd = 0; dd < 8; dd += 2) {
        float h0 = __bfloat162float(__float2bfloat16(acc[dd]));
        float h1 = __bfloat162float(__float2bfloat16(acc[dd + 1]));
        *(uint32_t*)(oh + ob + dd) = pack_bf2(acc[dd], acc[dd + 1]);
        *(uint32_t*)(ol + ob + dd) = pack_bf2(acc[dd] - h0, acc[dd + 1] - h1);
    }
}

// ===========================================================================
extern "C" void kernel_launch(void* const* d_in, const int* in_sizes, int n_in,
                              void* d_out, int out_size)
{
    const float* x    = (const float*)d_in[0];
    const float* c1w  = (const float*)d_in[1];
    const float* c1b  = (const float*)d_in[2];
    const float* rw1  = (const float*)d_in[3];
    const float* rb1  = (const float*)d_in[4];
    const float* rw2  = (const float*)d_in[5];
    const float* rb2  = (const float*)d_in[6];
    const float* ln1g = (const float*)d_in[7];
    const float* ln1b = (const float*)d_in[8];
    const float* qkvw = (const float*)d_in[9];
    const float* qkvb = (const float*)d_in[10];
    const float* rpb  = (const float*)d_in[11];
    const float* pw   = (const float*)d_in[12];
    const float* pb   = (const float*)d_in[13];
    const float* ln2g = (const float*)d_in[14];
    const float* ln2b = (const float*)d_in[15];
    const float* mw1  = (const float*)d_in[16];
    const float* mb1  = (const float*)d_in[17];
    const float* mw2  = (const float*)d_in[18];
    const float* mb2  = (const float*)d_in[19];
    const float* c2w  = (const float*)d_in[20];
    const float* c2b  = (const float*)d_in[21];
    float* out = (float*)d_out;

    float *y, *qkv, *t;
    __nv_bfloat16 *xh,*xl,*yh,*yl,*rh,*rl,*ch,*cl,*lh,*ll,*ah,*al,*uh,*ul,*th,*tl,*wth,*wtl;
    cudaGetSymbolAddress((void**)&y,   g_y);
    cudaGetSymbolAddress((void**)&qkv, g_qkv);
    cudaGetSymbolAddress((void**)&t,   g_t);
    cudaGetSymbolAddress((void**)&xh, g_xh); cudaGetSymbolAddress((void**)&xl, g_xl);
    cudaGetSymbolAddress((void**)&yh, g_yh); cudaGetSymbolAddress((void**)&yl, g_yl);
    cudaGetSymbolAddress((void**)&rh, g_rh); cudaGetSymbolAddress((void**)&rl, g_rl);
    cudaGetSymbolAddress((void**)&ch, g_ch); cudaGetSymbolAddress((void**)&cl, g_cl);
    cudaGetSymbolAddress((void**)&lh, g_lh); cudaGetSymbolAddress((void**)&ll, g_ll);
    cudaGetSymbolAddress((void**)&ah, g_ah); cudaGetSymbolAddress((void**)&al, g_al);
    cudaGetSymbolAddress((void**)&uh, g_uh); cudaGetSymbolAddress((void**)&ul, g_ul);
    cudaGetSymbolAddress((void**)&th, g_th); cudaGetSymbolAddress((void**)&tl, g_tl);
    cudaGetSymbolAddress((void**)&wth, g_wth); cudaGetSymbolAddress((void**)&wtl, g_wtl);

    cudaFuncSetAttribute(mm_k<0,0,1,1>, cudaFuncAttributeMaxDynamicSharedMemorySize, SMEM_TOTAL);
    cudaFuncSetAttribute(mm_k<2,3,0,1>, cudaFuncAttributeMaxDynamicSharedMemorySize, SMEM_TOTAL);
    cudaFuncSetAttribute(mm_k<2,4,0,1>, cudaFuncAttributeMaxDynamicSharedMemorySize, SMEM_TOTAL);
    cudaFuncSetAttribute(mm_k<0,0,1,0>, cudaFuncAttributeMaxDynamicSharedMemorySize, SMEM_TOTAL);
    cudaFuncSetAttribute(mm_k<0,2,1,0>, cudaFuncAttributeMaxDynamicSharedMemorySize, SMEM_TOTAL);
    cudaFuncSetAttribute(mm_k<0,1,0,1>, cudaFuncAttributeMaxDynamicSharedMemorySize, SMEM_TOTAL);
    cudaFuncSetAttribute(mm_k<0,2,0,1>, cudaFuncAttributeMaxDynamicSharedMemorySize, SMEM_TOTAL);
    cudaFuncSetAttribute(mm_k<1,2,1,0>, cudaFuncAttributeMaxDynamicSharedMemorySize, SMEM_TOTAL);

    // 0a. weight prep
    PrepArgs pa;
    pa.src[0]=c1w; pa.K[0]=256;  pa.N[0]=256; pa.off[0]=OFF_C1;
    pa.src[1]=rw1; pa.K[1]=1152; pa.N[1]=128; pa.off[1]=OFF_RW1;
    pa.src[2]=rw2; pa.K[2]=1152; pa.N[2]=128; pa.off[2]=OFF_RW2;
    pa.src[3]=qkvw;pa.K[3]=128;  pa.N[3]=384; pa.off[3]=OFF_QKV;
    pa.src[4]=pw;  pa.K[4]=128;  pa.N[4]=128; pa.off[4]=OFF_PW;
    pa.src[5]=mw1; pa.K[5]=128;  pa.N[5]=512; pa.off[5]=OFF_MW1;
    pa.src[6]=mw2; pa.K[6]=512;  pa.N[6]=128; pa.off[6]=OFF_MW2;
    pa.src[7]=c2w; pa.K[7]=256;  pa.N[7]=256; pa.off[7]=OFF_C2;
    prep_k<<<dim3(576, 8), 256>>>(pa, wth, wtl);
    // 0b. convert x
    cvt_k<<<32768, 256>>>(x, xh, xl, M_TOK * 64);

    const int M = M_TOK;
    // 1. conv1x1 #1: y(fp32 [M,256]) + ybf(cols 0-127)
    mm_k<0,0,1,1><<<dim3(M/128, 2), 256, SMEM_TOTAL>>>(
        xh, xl, nullptr, nullptr, 256, wth+OFF_C1, wtl+OFF_C1, 256,
        c1b, nullptr, 0, y, 256, yh, yl, 128);
    // 2. conv3x3 #1 + lrelu -> rbf
    mm_k<2,3,0,1><<<1024, 256, SMEM_TOTAL>>>(
        yh, yl, nullptr, nullptr, 128, wth+OFF_RW1, wtl+OFF_RW1, 1152,
        rb1, nullptr, 0, nullptr, 0, rh, rl, 128);
    // 3. conv3x3 #2 + lrelu + 2*conv_x -> cxbf
    mm_k<2,4,0,1><<<1024, 256, SMEM_TOTAL>>>(
        rh, rl, nullptr, nullptr, 128, wth+OFF_RW2, wtl+OFF_RW2, 1152,
        rb2, y, 256, nullptr, 0, ch, cl, 128);
    // 4. LN1 on trans_x -> lnbf
    ln_k<<<M/8, 256>>>(y + 128, 256, ln1g, ln1b, lh, ll);
    // 5. qkv (fp32)
    mm_k<0,0,1,0><<<dim3(M/128, 3), 256, SMEM_TOTAL>>>(
        lh, ll, nullptr, nullptr, 128, wth+OFF_QKV, wtl+OFF_QKV, 128,
        qkvb, nullptr, 0, qkv, 384, nullptr, nullptr, 0);
    // 6. attention -> attbf
    attn_k<<<8192, 256>>>(qkv, rpb, ah, al);
    // 7. proj + residual(trans_x) -> t (fp32)
    mm_k<0,2,1,0><<<dim3(M/128, 1), 256, SMEM_TOTAL>>>(
        ah, al, nullptr, nullptr, 128, wth+OFF_PW, wtl+OFF_PW, 128,
        pb, y + 128, 256, t, 128, nullptr, nullptr, 0);
    // 8. LN2 -> lnbf
    ln_k<<<M/8, 256>>>(t, 128, ln2g, ln2b, lh, ll);
    // 9. mlp1 + gelu -> ubf
    mm_k<0,1,0,1><<<dim3(M/128, 4), 256, SMEM_TOTAL>>>(
        lh, ll, nullptr, nullptr, 128, wth+OFF_MW1, wtl+OFF_MW1, 128,
        mb1, nullptr, 0, nullptr, 0, uh, ul, 512);
    // 10. mlp2 + residual(t) -> t2bf
    mm_k<0,2,0,1><<<dim3(M/128, 1), 256, SMEM_TOTAL>>>(
        uh, ul, nullptr, nullptr, 512, wth+OFF_MW2, wtl+OFF_MW2, 512,
        mb2, t, 128, nullptr, 0, th, tl, 128);
    // 11. conv1x1 #2 on concat(cx,t2) + x -> out
    mm_k<1,2,1,0><<<dim3(M/128, 2), 256, SMEM_TOTAL>>>(
        ch, cl, th, tl, 0, wth+OFF_C2, wtl+OFF_C2, 256,
        c2b, x, 256, out, 256, nullptr, nullptr, 0);
}

// round 7
// speedup vs baseline: 2.5302x; 1.1587x over previous
#include <cuda_runtime.h>
#include <cuda_bf16.h>
#include <math.h>
#include <stdint.h>

// ===========================================================================
// ConvTransBlock via legacy tensor-core path (mma.sync bf16, hi/lo split).
// B=2, H=W=256, C=256 (CD=128 | TD=128), WS=8, NH=4, HD=32.
// R7: 2 CTAs/SM (regs<=128 via a-register reuse + __launch_bounds__(256,2)).
// ===========================================================================

#define M_TOK 131072

// ---------------- fp32 buffers ----------------
__device__ float g_y  [131072 * 256];   // conv1 out
__device__ float g_qkv[131072 * 384];
__device__ float g_t  [131072 * 128];   // trans after proj residual

// ---------------- bf16 hi/lo activation buffers ----------------
__device__ __nv_bfloat16 g_xh[131072*256], g_xl[131072*256];
__device__ __nv_bfloat16 g_yh[131072*128], g_yl[131072*128];   // conv half of y
__device__ __nv_bfloat16 g_rh[131072*128], g_rl[131072*128];
__device__ __nv_bfloat16 g_ch[131072*128], g_cl[131072*128];   // cx
__device__ __nv_bfloat16 g_lh[131072*128], g_ll[131072*128];   // ln out
__device__ __nv_bfloat16 g_ah[131072*128], g_al[131072*128];   // attn out
__device__ __nv_bfloat16 g_uh[131072*512], g_ul[131072*512];   // mlp hidden
__device__ __nv_bfloat16 g_th[131072*128], g_tl[131072*128];   // t2

// transposed bf16 weights (hi / lo), K-major rows per n
#define WT_TOTAL 622592
__device__ __align__(256) __nv_bfloat16 g_wth[WT_TOTAL];
__device__ __align__(256) __nv_bfloat16 g_wtl[WT_TOTAL];
#define OFF_C1   0
#define OFF_RW1  65536
#define OFF_RW2  212992
#define OFF_QKV  360448
#define OFF_PW   409600
#define OFF_MW1  425984
#define OFF_MW2  491520
#define OFF_C2   557056

// ---------------- PTX helpers (all sm_80-compatible) ----------------
__device__ __forceinline__ uint32_t smem_u32(const void* p) {
    uint32_t a;
    asm("{ .reg .u64 t; cvta.to.shared.u64 t, %1; cvt.u32.u64 %0, t; }" : "=r"(a) : "l"(p));
    return a;
}
#define CP_ASYNC(dst, src, sz) \
    asm volatile("cp.async.cg.shared.global [%0], [%1], 16, %2;" \
        :: "r"(dst), "l"(src), "r"(sz))
#define CP_COMMIT() asm volatile("cp.async.commit_group;")
#define CP_WAIT(n)  asm volatile("cp.async.wait_group %0;" :: "n"(n))
#define LDM4(r, addr) \
    asm volatile("ldmatrix.sync.aligned.m8n8.x4.shared.b16 {%0,%1,%2,%3}, [%4];" \
        : "=r"((r)[0]), "=r"((r)[1]), "=r"((r)[2]), "=r"((r)[3]) : "r"(addr))
#define MMA(d, a, b0, b1) \
    asm volatile("mma.sync.aligned.m16n8k16.row.col.f32.bf16.bf16.f32 " \
        "{%0,%1,%2,%3}, {%4,%5,%6,%7}, {%8,%9}, {%0,%1,%2,%3};" \
        : "+f"((d)[0]), "+f"((d)[1]), "+f"((d)[2]), "+f"((d)[3]) \
        : "r"((a)[0]), "r"((a)[1]), "r"((a)[2]), "r"((a)[3]), "r"(b0), "r"(b1))

__device__ __forceinline__ uint32_t pack_bf2(float a, float b) {
    __nv_bfloat16 ha = __float2bfloat16(a), hb = __float2bfloat16(b);
    return ((uint32_t)__bfloat16_as_ushort(hb) << 16) | (uint32_t)__bfloat16_as_ushort(ha);
}

// ---------------- weight prep: W[k][n] -> Wt[n][k] bf16 hi/lo ----------------
struct PrepArgs { const float* src[8]; int K[8], N[8], off[8]; };
__global__ void __launch_bounds__(256) prep_k(PrepArgs a,
    __nv_bfloat16* __restrict__ dh, __nv_bfloat16* __restrict__ dl)
{
    int w = blockIdx.y;
    int K = a.K[w], N = a.N[w];
    int idx = blockIdx.x * 256 + threadIdx.x;
    if (idx >= K * N) return;
    int n = idx / K, k = idx - n * K;
    float v = a.src[w][(size_t)k * N + n];
    __nv_bfloat16 h = __float2bfloat16(v);
    dh[a.off[w] + idx] = h;
    dl[a.off[w] + idx] = __float2bfloat16(v - __bfloat162float(h));
}

// ---------------- fp32 -> bf16 hi/lo converter (for x) ----------------
__global__ void __launch_bounds__(256) cvt_k(const float* __restrict__ in,
    __nv_bfloat16* __restrict__ oh, __nv_bfloat16* __restrict__ ol, int n4)
{
    int i = blockIdx.x * 256 + threadIdx.x;
    if (i >= n4) return;
    float4 v = ((const float4*)in)[i];
    float h0 = __bfloat162float(__float2bfloat16(v.x));
    float h1 = __bfloat162float(__float2bfloat16(v.y));
    float h2 = __bfloat162float(__float2bfloat16(v.z));
    float h3 = __bfloat162float(__float2bfloat16(v.w));
    uint2 H = make_uint2(pack_bf2(v.x, v.y), pack_bf2(v.z, v.w));
    uint2 L = make_uint2(pack_bf2(v.x - h0, v.y - h1), pack_bf2(v.z - h2, v.w - h3));
    ((uint2*)oh)[i] = H;
    ((uint2*)ol)[i] = L;
}

// ---------------- unified tensor-core GEMM / implicit-GEMM conv ----------------
// MODE: 0 gemm, 1 concat(A0bf,A1bf) along K, 2 conv3x3 (A = [M,128] bf16, halo)
// EPI:  0 bias; 1 bias+gelu; 2 bias+res; 3 bias+lrelu; 4 bias+lrelu+2*res
// WF:   write fp32 out;  WBF: write bf16 hi/lo out (cols < ldob)
#define RS 80                      // smem row stride bytes (32 bf16 + pad)
#define STAGE_SZ 40960             // AH 10240 | AL 10240 | BH 10240 | BL 10240
#define SMEM_TOTAL (2 * STAGE_SZ)

template<int MODE, int EPI, int WF, int WBF>
__global__ void __launch_bounds__(256, 2) mm_k(
    const __nv_bfloat16* __restrict__ AH0, const __nv_bfloat16* __restrict__ AL0,
    const __nv_bfloat16* __restrict__ AH1, const __nv_bfloat16* __restrict__ AL1,
    int ldA,
    const __nv_bfloat16* __restrict__ WH, const __nv_bfloat16* __restrict__ WL,
    int Kw,
    const float* __restrict__ bias,
    const float* __restrict__ res, int ldRes,
    float* __restrict__ out, int ldo,
    __nv_bfloat16* __restrict__ obH, __nv_bfloat16* __restrict__ obL, int ldob)
{
    extern __shared__ char sm[];
    const uint32_t sb = smem_u32(sm);
    const int tid = threadIdx.x;
    const int wid = tid >> 5;
    const int lane = tid & 31;
    const int nc = Kw >> 5;

    int m0 = 0, n0 = 0, bB = 0, gh0 = 0, gw0 = 0;
    if (MODE == 2) {
        bB  = blockIdx.x >> 9;
        gh0 = ((blockIdx.x >> 4) & 31) * 8;
        gw0 = (blockIdx.x & 15) * 16;
    } else {
        m0 = blockIdx.x * 128;
        n0 = blockIdx.y * 128;
    }

    // loader mapping: 2 threads per row, each covers a 32B k-half (2x16B)
    const int lr = tid >> 1;
    const int lh = tid & 1;
    int lph = 0, lpw = 0;
    if (MODE == 2) { lph = gh0 + (lr >> 4); lpw = gw0 + (lr & 15); }

    auto issue_chunk = [&](int cc) {
        const int s = cc & 1;
        const uint32_t base = sb + s * STAGE_SZ;
        const int kin = cc * 32;
        // ---- A ----
        const __nv_bfloat16 *ah, *al;
        uint32_t asz = 16;
        if (MODE == 0) {
            ah = AH0 + (size_t)(m0 + lr) * ldA + kin;
            al = AL0 + (size_t)(m0 + lr) * ldA + kin;
        } else if (MODE == 1) {
            if (kin < 128) {
                ah = AH0 + (size_t)(m0 + lr) * 128 + kin;
                al = AL0 + (size_t)(m0 + lr) * 128 + kin;
            } else {
                ah = AH1 + (size_t)(m0 + lr) * 128 + (kin - 128);
                al = AL1 + (size_t)(m0 + lr) * 128 + (kin - 128);
            }
        } else {
            const int tap = cc >> 2, kk = (cc & 3) * 32;
            const int ih = lph + tap / 3 - 1, iw = lpw + tap % 3 - 1;
            const bool ok = ((unsigned)ih < 256u) && ((unsigned)iw < 256u);
            const size_t pix = ok ? (size_t)((bB * 256 + ih) * 256 + iw) : 0;
            ah = AH0 + pix * 128 + kk;
            al = AL0 + pix * 128 + kk;
            asz = ok ? 16u : 0u;
        }
        const uint32_t da = base + (uint32_t)lr * RS + lh * 32;
        CP_ASYNC(da,              (const char*)ah + lh * 32,      asz);
        CP_ASYNC(da + 16,         (const char*)ah + lh * 32 + 16, asz);
        CP_ASYNC(da + 10240,      (const char*)al + lh * 32,      asz);
        CP_ASYNC(da + 10240 + 16, (const char*)al + lh * 32 + 16, asz);
        // ---- B (weights, K-major rows) ----
        const __nv_bfloat16* bh = WH + (size_t)(n0 + lr) * Kw + kin;
        const __nv_bfloat16* bl = WL + (size_t)(n0 + lr) * Kw + kin;
        const uint32_t db = base + 20480 + (uint32_t)lr * RS + lh * 32;
        CP_ASYNC(db,              (const char*)bh + lh * 32,      16);
        CP_ASYNC(db + 16,         (const char*)bh + lh * 32 + 16, 16);
        CP_ASYNC(db + 10240,      (const char*)bl + lh * 32,      16);
        CP_ASYNC(db + 10240 + 16, (const char*)bl + lh * 32 + 16, 16);
    };

    // warp tiling: warp_m in {0,1} (64 rows), warp_n in {0..3} (32 cols)
    const int wm = (wid & 1) * 64;
    const int wn = (wid >> 1) * 32;
    const uint32_t a_lo = (uint32_t)(lane & 15) * RS + (uint32_t)(lane >> 4) * 16;
    const uint32_t b_lo = (uint32_t)((lane & 7) + ((lane >> 4) << 3)) * RS
                        + (uint32_t)((lane >> 3) & 1) * 16;

    float acc[4][4][4] = {};

    issue_chunk(0);
    CP_COMMIT();

    for (int c = 0; c < nc; c++) {
        if (c + 1 < nc) { issue_chunk(c + 1); CP_COMMIT(); CP_WAIT(1); }
        else            { CP_WAIT(0); }
        __syncthreads();

        const uint32_t base = sb + (c & 1) * STAGE_SZ;
        #pragma unroll
        for (int ks = 0; ks < 2; ks++) {
            // a-register reuse: aR holds aH for s0/s1, then aL for s2.
            // Live set: acc(64) + aR(16) + bH(8) + bL(8)  ->  fits 128 regs
            // with __launch_bounds__(256,2)  =>  2 CTAs/SM.
            uint32_t aR[4][4], bH[2][4], bL[2][4];
            #pragma unroll
            for (int bg = 0; bg < 2; bg++) {
                const uint32_t bd = base + 20480 + (uint32_t)(wn + bg * 16) * RS + ks * 32 + b_lo;
                LDM4(bH[bg], bd);
                LDM4(bL[bg], bd + 10240);
            }
            #pragma unroll
            for (int mi = 0; mi < 4; mi++) {
                const uint32_t ad = base + (uint32_t)(wm + mi * 16) * RS + ks * 32 + a_lo;
                LDM4(aR[mi], ad);
            }
            // s0: aH * bH
            #pragma unroll
            for (int mi = 0; mi < 4; mi++)
                #pragma unroll
                for (int nj = 0; nj < 4; nj++) {
                    const uint32_t* bf = &bH[nj >> 1][(nj & 1) * 2];
                    MMA(acc[mi][nj], aR[mi], bf[0], bf[1]);
                }
            // s1: aH * bL
            #pragma unroll
            for (int mi = 0; mi < 4; mi++)
                #pragma unroll
                for (int nj = 0; nj < 4; nj++) {
                    const uint32_t* bf = &bL[nj >> 1][(nj & 1) * 2];
                    MMA(acc[mi][nj], aR[mi], bf[0], bf[1]);
                }
            // reload aR with aL
            #pragma unroll
            for (int mi = 0; mi < 4; mi++) {
                const uint32_t ad = base + (uint32_t)(wm + mi * 16) * RS + ks * 32 + a_lo;
                LDM4(aR[mi], ad + 10240);
            }
            // s2: aL * bH
            #pragma unroll
            for (int mi = 0; mi < 4; mi++)
                #pragma unroll
                for (int nj = 0; nj < 4; nj++) {
                    const uint32_t* bf = &bH[nj >> 1][(nj & 1) * 2];
                    MMA(acc[mi][nj], aR[mi], bf[0], bf[1]);
                }
        }
        __syncthreads();
    }

    // ---- epilogue ----
    #pragma unroll
    for (int mi = 0; mi < 4; mi++) {
        #pragma unroll
        for (int h2 = 0; h2 < 2; h2++) {
            const int r = wm + mi * 16 + (lane >> 2) + h2 * 8;
            size_t orow;
            if (MODE == 2)
                orow = (size_t)((bB * 256 + gh0 + (r >> 4)) * 256 + gw0 + (r & 15));
            else
                orow = (size_t)(m0 + r);
            #pragma unroll
            for (int nj = 0; nj < 4; nj++) {
                const int n = n0 + wn + nj * 8 + (lane & 3) * 2;
                float v0 = acc[mi][nj][h2 * 2 + 0] + __ldg(&bias[n]);
                float v1 = acc[mi][nj][h2 * 2 + 1] + __ldg(&bias[n + 1]);
                if (EPI == 1) {
                    v0 = 0.5f * v0 * (1.0f + erff(v0 * 0.7071067811865476f));
                    v1 = 0.5f * v1 * (1.0f + erff(v1 * 0.7071067811865476f));
                }
                if (EPI == 3 || EPI == 4) {
                    v0 = v0 >= 0.f ? v0 : 0.01f * v0;
                    v1 = v1 >= 0.f ? v1 : 0.01f * v1;
                }
                if (EPI == 2) {
                    const float2 rv = *(const float2*)(res + orow * ldRes + n);
                    v0 += rv.x; v1 += rv.y;
                }
                if (EPI == 4) {
                    const float2 rv = *(const float2*)(res + orow * ldRes + n);
                    v0 += 2.f * rv.x; v1 += 2.f * rv.y;
                }
                if (WF)
                    *(float2*)(out + orow * ldo + n) = make_float2(v0, v1);
                if (WBF && n < ldob) {
                    float h0 = __bfloat162float(__float2bfloat16(v0));
                    float h1 = __bfloat162float(__float2bfloat16(v1));
                    *(uint32_t*)(obH + orow * ldob + n) = pack_bf2(v0, v1);
                    *(uint32_t*)(obL + orow * ldob + n) = pack_bf2(v0 - h0, v1 - h1);
                }
            }
        }
    }
}

// ---------------- LayerNorm (fp32 in, bf16 hi/lo out) ----------------
__global__ void __launch_bounds__(256) ln_k(
    const float* __restrict__ in, int stride,
    const float* __restrict__ g, const float* __restrict__ bta,
    __nv_bfloat16* __restrict__ oh, __nv_bfloat16* __restrict__ ol)
{
    const int token = blockIdx.x * 8 + (threadIdx.x >> 5);
    const int lane = threadIdx.x & 31;
    const float* p = in + (size_t)token * stride;
    float4 v = *(const float4*)(p + lane * 4);
    float s  = v.x + v.y + v.z + v.w;
    float sq = v.x * v.x + v.y * v.y + v.z * v.z + v.w * v.w;
    #pragma unroll
    for (int o = 16; o; o >>= 1) {
        s  += __shfl_xor_sync(0xffffffffu, s,  o);
        sq += __shfl_xor_sync(0xffffffffu, sq, o);
    }
    const float mu  = s * (1.0f / 128.0f);
    const float var = sq * (1.0f / 128.0f) - mu * mu;
    const float rs  = rsqrtf(var + 1e-5f);
    float4 gv = *(const float4*)(g + lane * 4);
    float4 bv = *(const float4*)(bta + lane * 4);
    float o0 = (v.x - mu) * rs * gv.x + bv.x;
    float o1 = (v.y - mu) * rs * gv.y + bv.y;
    float o2 = (v.z - mu) * rs * gv.z + bv.z;
    float o3 = (v.w - mu) * rs * gv.w + bv.w;
    float h0 = __bfloat162float(__float2bfloat16(o0));
    float h1 = __bfloat162float(__float2bfloat16(o1));
    float h2 = __bfloat162float(__float2bfloat16(o2));
    float h3 = __bfloat162float(__float2bfloat16(o3));
    const size_t off = (size_t)token * 128 + lane * 4;
    *(uint2*)(oh + off) = make_uint2(pack_bf2(o0, o1), pack_bf2(o2, o3));
    *(uint2*)(ol + off) = make_uint2(pack_bf2(o0 - h0, o1 - h1), pack_bf2(o2 - h2, o3 - h3));
}

// ---------------- windowed attention (fp32; bf16 hi/lo out) ----------------
__global__ void __launch_bounds__(256) attn_k(
    const float* __restrict__ qkv, const float* __restrict__ rpb,
    __nv_bfloat16* __restrict__ oh, __nv_bfloat16* __restrict__ ol)
{
    __shared__ float qs[64][32];
    __shared__ float ks[64][33];
    __shared__ float vs[64][33];
    __shared__ float Ps[64][65];
    __shared__ int pixS[64];
    __shared__ int ridS[64];

    const int tid = threadIdx.x;
    const int head = blockIdx.x & 3;
    const int w = (blockIdx.x >> 2) & 1023;
    const int b = blockIdx.x >> 12;
    const int wi = w >> 5, wj = w & 31;

    if (tid < 64) {
        const int ti = tid >> 3, tj = tid & 7;
        const int hh = wi * 8 + ti, ww = wj * 8 + tj;
        pixS[tid] = (b * 256 + ((hh + 4) & 255)) * 256 + ((ww + 4) & 255);
        const int rh = hh < 248 ? 0 : (hh < 252 ? 1 : 2);
        const int rw = ww < 248 ? 0 : (ww < 252 ? 1 : 2);
        ridS[tid] = rh * 3 + rw;
    }
    __syncthreads();

    const int ho = head * 32;
    for (int idx = tid; idx < 2048; idx += 256) {
        const int t = idx >> 5, d = idx & 31;
        const size_t base = (size_t)pixS[t] * 384 + ho + d;
        qs[t][d] = qkv[base];
        ks[t][d] = qkv[base + 128];
        vs[t][d] = qkv[base + 256];
    }
    __syncthreads();

    const int warp = tid >> 5, lane = tid & 31;
    #pragma unroll
    for (int rr = 0; rr < 8; rr++) {
        const int r = warp * 8 + rr;
        float s0 = 0.f, s1 = 0.f;
        #pragma unroll
        for (int d = 0; d < 32; d++) {
            const float qv = qs[r][d];
            s0 += qv * ks[lane][d];
            s1 += qv * ks[lane + 32][d];
        }
        const int ri = r >> 3, rj = r & 7;
        const int rid_r = ridS[r];
        {
            const int c = lane;
            const int rel = (ri - (c >> 3) + 7) * 15 + (rj - (c & 7) + 7);
            s0 = s0 * 0.17677669529663687f + rpb[rel * 4 + head];
            if (rid_r != ridS[c]) s0 -= 1e9f;
        }
        {
            const int c = lane + 32;
            const int rel = (ri - (c >> 3) + 7) * 15 + (rj - (c & 7) + 7);
            s1 = s1 * 0.17677669529663687f + rpb[rel * 4 + head];
            if (rid_r != ridS[c]) s1 -= 1e9f;
        }
        float mx = fmaxf(s0, s1);
        #pragma unroll
        for (int o = 16; o; o >>= 1) mx = fmaxf(mx, __shfl_xor_sync(0xffffffffu, mx, o));
        float e0 = expf(s0 - mx), e1 = expf(s1 - mx);
        float sm = e0 + e1;
        #pragma unroll
        for (int o = 16; o; o >>= 1) sm += __shfl_xor_sync(0xffffffffu, sm, o);
        const float inv = 1.0f / sm;
        Ps[r][lane] = e0 * inv;
        Ps[r][lane + 32] = e1 * inv;
    }
    __syncthreads();

    const int i = tid >> 2, d0 = (tid & 3) * 8;
    float acc[8] = {};
    #pragma unroll
    for (int j = 0; j < 64; j++) {
        const float p = Ps[i][j];
        #pragma unroll
        for (int dd = 0; dd < 8; dd++) acc[dd] += p * vs[j][d0 + dd];
    }
    const size_t ob = (size_t)pixS[i] * 128 + ho + d0;
    #pragma unroll
    for (int dd = 0; dd < 8; dd += 2) {
        float h0 = __bfloat162float(__float2bfloat16(acc[dd]));
        float h1 = __bfloat162float(__float2bfloat16(acc[dd + 1]));
        *(uint32_t*)(oh + ob + dd) = pack_bf2(acc[dd], acc[dd + 1]);
        *(uint32_t*)(ol + ob + dd) = pack_bf2(acc[dd] - h0, acc[dd + 1] - h1);
    }
}

// ===========================================================================
extern "C" void kernel_launch(void* const* d_in, const int* in_sizes, int n_in,
                              void* d_out, int out_size)
{
    const float* x    = (const float*)d_in[0];
    const float* c1w  = (const float*)d_in[1];
    const float* c1b  = (const float*)d_in[2];
    const float* rw1  = (const float*)d_in[3];
    const float* rb1  = (const float*)d_in[4];
    const float* rw2  = (const float*)d_in[5];
    const float* rb2  = (const float*)d_in[6];
    const float* ln1g = (const float*)d_in[7];
    const float* ln1b = (const float*)d_in[8];
    const float* qkvw = (const float*)d_in[9];
    const float* qkvb = (const float*)d_in[10];
    const float* rpb  = (const float*)d_in[11];
    const float* pw   = (const float*)d_in[12];
    const float* pb   = (const float*)d_in[13];
    const float* ln2g = (const float*)d_in[14];
    const float* ln2b = (const float*)d_in[15];
    const float* mw1  = (const float*)d_in[16];
    const float* mb1  = (const float*)d_in[17];
    const float* mw2  = (const float*)d_in[18];
    const float* mb2  = (const float*)d_in[19];
    const float* c2w  = (const float*)d_in[20];
    const float* c2b  = (const float*)d_in[21];
    float* out = (float*)d_out;

    float *y, *qkv, *t;
    __nv_bfloat16 *xh,*xl,*yh,*yl,*rh,*rl,*ch,*cl,*lh,*ll,*ah,*al,*uh,*ul,*th,*tl,*wth,*wtl;
    cudaGetSymbolAddress((void**)&y,   g_y);
    cudaGetSymbolAddress((void**)&qkv, g_qkv);
    cudaGetSymbolAddress((void**)&t,   g_t);
    cudaGetSymbolAddress((void**)&xh, g_xh); cudaGetSymbolAddress((void**)&xl, g_xl);
    cudaGetSymbolAddress((void**)&yh, g_yh); cudaGetSymbolAddress((void**)&yl, g_yl);
    cudaGetSymbolAddress((void**)&rh, g_rh); cudaGetSymbolAddress((void**)&rl, g_rl);
    cudaGetSymbolAddress((void**)&ch, g_ch); cudaGetSymbolAddress((void**)&cl, g_cl);
    cudaGetSymbolAddress((void**)&lh, g_lh); cudaGetSymbolAddress((void**)&ll, g_ll);
    cudaGetSymbolAddress((void**)&ah, g_ah); cudaGetSymbolAddress((void**)&al, g_al);
    cudaGetSymbolAddress((void**)&uh, g_uh); cudaGetSymbolAddress((void**)&ul, g_ul);
    cudaGetSymbolAddress((void**)&th, g_th); cudaGetSymbolAddress((void**)&tl, g_tl);
    cudaGetSymbolAddress((void**)&wth, g_wth); cudaGetSymbolAddress((void**)&wtl, g_wtl);

    cudaFuncSetAttribute(mm_k<0,0,1,1>, cudaFuncAttributeMaxDynamicSharedMemorySize, SMEM_TOTAL);
    cudaFuncSetAttribute(mm_k<2,3,0,1>, cudaFuncAttributeMaxDynamicSharedMemorySize, SMEM_TOTAL);
    cudaFuncSetAttribute(mm_k<2,4,0,1>, cudaFuncAttributeMaxDynamicSharedMemorySize, SMEM_TOTAL);
    cudaFuncSetAttribute(mm_k<0,0,1,0>, cudaFuncAttributeMaxDynamicSharedMemorySize, SMEM_TOTAL);
    cudaFuncSetAttribute(mm_k<0,2,1,0>, cudaFuncAttributeMaxDynamicSharedMemorySize, SMEM_TOTAL);
    cudaFuncSetAttribute(mm_k<0,1,0,1>, cudaFuncAttributeMaxDynamicSharedMemorySize, SMEM_TOTAL);
    cudaFuncSetAttribute(mm_k<0,2,0,1>, cudaFuncAttributeMaxDynamicSharedMemorySize, SMEM_TOTAL);
    cudaFuncSetAttribute(mm_k<1,2,1,0>, cudaFuncAttributeMaxDynamicSharedMemorySize, SMEM_TOTAL);

    // 0a. weight prep
    PrepArgs pa;
    pa.src[0]=c1w; pa.K[0]=256;  pa.N[0]=256; pa.off[0]=OFF_C1;
    pa.src[1]=rw1; pa.K[1]=1152; pa.N[1]=128; pa.off[1]=OFF_RW1;
    pa.src[2]=rw2; pa.K[2]=1152; pa.N[2]=128; pa.off[2]=OFF_RW2;
    pa.src[3]=qkvw;pa.K[3]=128;  pa.N[3]=384; pa.off[3]=OFF_QKV;
    pa.src[4]=pw;  pa.K[4]=128;  pa.N[4]=128; pa.off[4]=OFF_PW;
    pa.src[5]=mw1; pa.K[5]=128;  pa.N[5]=512; pa.off[5]=OFF_MW1;
    pa.src[6]=mw2; pa.K[6]=512;  pa.N[6]=128; pa.off[6]=OFF_MW2;
    pa.src[7]=c2w; pa.K[7]=256;  pa.N[7]=256; pa.off[7]=OFF_C2;
    prep_k<<<dim3(576, 8), 256>>>(pa, wth, wtl);
    // 0b. convert x
    cvt_k<<<32768, 256>>>(x, xh, xl, M_TOK * 64);

    const int M = M_TOK;
    // 1. conv1x1 #1: y(fp32 [M,256]) + ybf(cols 0-127)
    mm_k<0,0,1,1><<<dim3(M/128, 2), 256, SMEM_TOTAL>>>(
        xh, xl, nullptr, nullptr, 256, wth+OFF_C1, wtl+OFF_C1, 256,
        c1b, nullptr, 0, y, 256, yh, yl, 128);
    // 2. conv3x3 #1 + lrelu -> rbf
    mm_k<2,3,0,1><<<1024, 256, SMEM_TOTAL>>>(
        yh, yl, nullptr, nullptr, 128, wth+OFF_RW1, wtl+OFF_RW1, 1152,
        rb1, nullptr, 0, nullptr, 0, rh, rl, 128);
    // 3. conv3x3 #2 + lrelu + 2*conv_x -> cxbf
    mm_k<2,4,0,1><<<1024, 256, SMEM_TOTAL>>>(
        rh, rl, nullptr, nullptr, 128, wth+OFF_RW2, wtl+OFF_RW2, 1152,
        rb2, y, 256, nullptr, 0, ch, cl, 128);
    // 4. LN1 on trans_x -> lnbf
    ln_k<<<M/8, 256>>>(y + 128, 256, ln1g, ln1b, lh, ll);
    // 5. qkv (fp32)
    mm_k<0,0,1,0><<<dim3(M/128, 3), 256, SMEM_TOTAL>>>(
        lh, ll, nullptr, nullptr, 128, wth+OFF_QKV, wtl+OFF_QKV, 128,
        qkvb, nullptr, 0, qkv, 384, nullptr, nullptr, 0);
    // 6. attention -> attbf
    attn_k<<<8192, 256>>>(qkv, rpb, ah, al);
    // 7. proj + residual(trans_x) -> t (fp32)
    mm_k<0,2,1,0><<<dim3(M/128, 1), 256, SMEM_TOTAL>>>(
        ah, al, nullptr, nullptr, 128, wth+OFF_PW, wtl+OFF_PW, 128,
        pb, y + 128, 256, t, 128, nullptr, nullptr, 0);
    // 8. LN2 -> lnbf
    ln_k<<<M/8, 256>>>(t, 128, ln2g, ln2b, lh, ll);
    // 9. mlp1 + gelu -> ubf
    mm_k<0,1,0,1><<<dim3(M/128, 4), 256, SMEM_TOTAL>>>(
        lh, ll, nullptr, nullptr, 128, wth+OFF_MW1, wtl+OFF_MW1, 128,
        mb1, nullptr, 0, nullptr, 0, uh, ul, 512);
    // 10. mlp2 + residual(t) -> t2bf
    mm_k<0,2,0,1><<<dim3(M/128, 1), 256, SMEM_TOTAL>>>(
        uh, ul, nullptr, nullptr, 512, wth+OFF_MW2, wtl+OFF_MW2, 512,
        mb2, t, 128, nullptr, 0, th, tl, 128);
    // 11. conv1x1 #2 on concat(cx,t2) + x -> out
    mm_k<1,2,1,0><<<dim3(M/128, 2), 256, SMEM_TOTAL>>>(
        ch, cl, th, tl, 0, wth+OFF_C2, wtl+OFF_C2, 256,
        c2b, x, 256, out, 256, nullptr, nullptr, 0);
}

// round 8
// speedup vs baseline: 2.7244x; 1.0767x over previous
#include <cuda_runtime.h>
#include <cuda_bf16.h>
#include <math.h>
#include <stdint.h>

// ===========================================================================
// ConvTransBlock via legacy tensor-core path (mma.sync bf16, hi/lo split).
// B=2, H=W=256, C=256 (CD=128 | TD=128), WS=8, NH=4, HD=32.
// R8: single __syncthreads per k-chunk + dual-stream fork/join overlap.
// ===========================================================================

#define M_TOK 131072

// ---------------- fp32 buffers ----------------
__device__ float g_y  [131072 * 256];   // conv1 out
__device__ float g_qkv[131072 * 384];
__device__ float g_t  [131072 * 128];   // trans after proj residual

// ---------------- bf16 hi/lo activation buffers ----------------
__device__ __nv_bfloat16 g_xh[131072*256], g_xl[131072*256];
__device__ __nv_bfloat16 g_yh[131072*128], g_yl[131072*128];   // conv half of y
__device__ __nv_bfloat16 g_rh[131072*128], g_rl[131072*128];
__device__ __nv_bfloat16 g_ch[131072*128], g_cl[131072*128];   // cx
__device__ __nv_bfloat16 g_lh[131072*128], g_ll[131072*128];   // ln out
__device__ __nv_bfloat16 g_ah[131072*128], g_al[131072*128];   // attn out
__device__ __nv_bfloat16 g_uh[131072*512], g_ul[131072*512];   // mlp hidden
__device__ __nv_bfloat16 g_th[131072*128], g_tl[131072*128];   // t2

// transposed bf16 weights (hi / lo), K-major rows per n
#define WT_TOTAL 622592
__device__ __align__(256) __nv_bfloat16 g_wth[WT_TOTAL];
__device__ __align__(256) __nv_bfloat16 g_wtl[WT_TOTAL];
#define OFF_C1   0
#define OFF_RW1  65536
#define OFF_RW2  212992
#define OFF_QKV  360448
#define OFF_PW   409600
#define OFF_MW1  425984
#define OFF_MW2  491520
#define OFF_C2   557056

// ---------------- PTX helpers (all sm_80-compatible) ----------------
__device__ __forceinline__ uint32_t smem_u32(const void* p) {
    uint32_t a;
    asm("{ .reg .u64 t; cvta.to.shared.u64 t, %1; cvt.u32.u64 %0, t; }" : "=r"(a) : "l"(p));
    return a;
}
#define CP_ASYNC(dst, src, sz) \
    asm volatile("cp.async.cg.shared.global [%0], [%1], 16, %2;" \
        :: "r"(dst), "l"(src), "r"(sz))
#define CP_COMMIT() asm volatile("cp.async.commit_group;")
#define CP_WAIT(n)  asm volatile("cp.async.wait_group %0;" :: "n"(n))
#define LDM4(r, addr) \
    asm volatile("ldmatrix.sync.aligned.m8n8.x4.shared.b16 {%0,%1,%2,%3}, [%4];" \
        : "=r"((r)[0]), "=r"((r)[1]), "=r"((r)[2]), "=r"((r)[3]) : "r"(addr))
#define MMA(d, a, b0, b1) \
    asm volatile("mma.sync.aligned.m16n8k16.row.col.f32.bf16.bf16.f32 " \
        "{%0,%1,%2,%3}, {%4,%5,%6,%7}, {%8,%9}, {%0,%1,%2,%3};" \
        : "+f"((d)[0]), "+f"((d)[1]), "+f"((d)[2]), "+f"((d)[3]) \
        : "r"((a)[0]), "r"((a)[1]), "r"((a)[2]), "r"((a)[3]), "r"(b0), "r"(b1))

__device__ __forceinline__ uint32_t pack_bf2(float a, float b) {
    __nv_bfloat16 ha = __float2bfloat16(a), hb = __float2bfloat16(b);
    return ((uint32_t)__bfloat16_as_ushort(hb) << 16) | (uint32_t)__bfloat16_as_ushort(ha);
}

// ---------------- weight prep: W[k][n] -> Wt[n][k] bf16 hi/lo ----------------
struct PrepArgs { const float* src[8]; int K[8], N[8], off[8]; };
__global__ void __launch_bounds__(256) prep_k(PrepArgs a,
    __nv_bfloat16* __restrict__ dh, __nv_bfloat16* __restrict__ dl)
{
    int w = blockIdx.y;
    int K = a.K[w], N = a.N[w];
    int idx = blockIdx.x * 256 + threadIdx.x;
    if (idx >= K * N) return;
    int n = idx / K, k = idx - n * K;
    float v = a.src[w][(size_t)k * N + n];
    __nv_bfloat16 h = __float2bfloat16(v);
    dh[a.off[w] + idx] = h;
    dl[a.off[w] + idx] = __float2bfloat16(v - __bfloat162float(h));
}

// ---------------- fp32 -> bf16 hi/lo converter (for x) ----------------
__global__ void __launch_bounds__(256) cvt_k(const float* __restrict__ in,
    __nv_bfloat16* __restrict__ oh, __nv_bfloat16* __restrict__ ol, int n4)
{
    int i = blockIdx.x * 256 + threadIdx.x;
    if (i >= n4) return;
    float4 v = ((const float4*)in)[i];
    float h0 = __bfloat162float(__float2bfloat16(v.x));
    float h1 = __bfloat162float(__float2bfloat16(v.y));
    float h2 = __bfloat162float(__float2bfloat16(v.z));
    float h3 = __bfloat162float(__float2bfloat16(v.w));
    uint2 H = make_uint2(pack_bf2(v.x, v.y), pack_bf2(v.z, v.w));
    uint2 L = make_uint2(pack_bf2(v.x - h0, v.y - h1), pack_bf2(v.z - h2, v.w - h3));
    ((uint2*)oh)[i] = H;
    ((uint2*)ol)[i] = L;
}

// ---------------- unified tensor-core GEMM / implicit-GEMM conv ----------------
// MODE: 0 gemm, 1 concat(A0bf,A1bf) along K, 2 conv3x3 (A = [M,128] bf16, halo)
// EPI:  0 bias; 1 bias+gelu; 2 bias+res; 3 bias+lrelu; 4 bias+lrelu+2*res
// WF:   write fp32 out;  WBF: write bf16 hi/lo out (cols < ldob)
#define RS 80                      // smem row stride bytes (32 bf16 + pad)
#define STAGE_SZ 40960             // AH 10240 | AL 10240 | BH 10240 | BL 10240
#define SMEM_TOTAL (2 * STAGE_SZ)

template<int MODE, int EPI, int WF, int WBF>
__global__ void __launch_bounds__(256, 2) mm_k(
    const __nv_bfloat16* __restrict__ AH0, const __nv_bfloat16* __restrict__ AL0,
    const __nv_bfloat16* __restrict__ AH1, const __nv_bfloat16* __restrict__ AL1,
    int ldA,
    const __nv_bfloat16* __restrict__ WH, const __nv_bfloat16* __restrict__ WL,
    int Kw,
    const float* __restrict__ bias,
    const float* __restrict__ res, int ldRes,
    float* __restrict__ out, int ldo,
    __nv_bfloat16* __restrict__ obH, __nv_bfloat16* __restrict__ obL, int ldob)
{
    extern __shared__ char sm[];
    const uint32_t sb = smem_u32(sm);
    const int tid = threadIdx.x;
    const int wid = tid >> 5;
    const int lane = tid & 31;
    const int nc = Kw >> 5;

    int m0 = 0, n0 = 0, bB = 0, gh0 = 0, gw0 = 0;
    if (MODE == 2) {
        bB  = blockIdx.x >> 9;
        gh0 = ((blockIdx.x >> 4) & 31) * 8;
        gw0 = (blockIdx.x & 15) * 16;
    } else {
        m0 = blockIdx.x * 128;
        n0 = blockIdx.y * 128;
    }

    // loader mapping: 2 threads per row, each covers a 32B k-half (2x16B)
    const int lr = tid >> 1;
    const int lh = tid & 1;
    int lph = 0, lpw = 0;
    if (MODE == 2) { lph = gh0 + (lr >> 4); lpw = gw0 + (lr & 15); }

    auto issue_chunk = [&](int cc) {
        const int s = cc & 1;
        const uint32_t base = sb + s * STAGE_SZ;
        const int kin = cc * 32;
        // ---- A ----
        const __nv_bfloat16 *ah, *al;
        uint32_t asz = 16;
        if (MODE == 0) {
            ah = AH0 + (size_t)(m0 + lr) * ldA + kin;
            al = AL0 + (size_t)(m0 + lr) * ldA + kin;
        } else if (MODE == 1) {
            if (kin < 128) {
                ah = AH0 + (size_t)(m0 + lr) * 128 + kin;
                al = AL0 + (size_t)(m0 + lr) * 128 + kin;
            } else {
                ah = AH1 + (size_t)(m0 + lr) * 128 + (kin - 128);
                al = AL1 + (size_t)(m0 + lr) * 128 + (kin - 128);
            }
        } else {
            const int tap = cc >> 2, kk = (cc & 3) * 32;
            const int ih = lph + tap / 3 - 1, iw = lpw + tap % 3 - 1;
            const bool ok = ((unsigned)ih < 256u) && ((unsigned)iw < 256u);
            const size_t pix = ok ? (size_t)((bB * 256 + ih) * 256 + iw) : 0;
            ah = AH0 + pix * 128 + kk;
            al = AL0 + pix * 128 + kk;
            asz = ok ? 16u : 0u;
        }
        const uint32_t da = base + (uint32_t)lr * RS + lh * 32;
        CP_ASYNC(da,              (const char*)ah + lh * 32,      asz);
        CP_ASYNC(da + 16,         (const char*)ah + lh * 32 + 16, asz);
        CP_ASYNC(da + 10240,      (const char*)al + lh * 32,      asz);
        CP_ASYNC(da + 10240 + 16, (const char*)al + lh * 32 + 16, asz);
        // ---- B (weights, K-major rows) ----
        const __nv_bfloat16* bh = WH + (size_t)(n0 + lr) * Kw + kin;
        const __nv_bfloat16* bl = WL + (size_t)(n0 + lr) * Kw + kin;
        const uint32_t db = base + 20480 + (uint32_t)lr * RS + lh * 32;
        CP_ASYNC(db,              (const char*)bh + lh * 32,      16);
        CP_ASYNC(db + 16,         (const char*)bh + lh * 32 + 16, 16);
        CP_ASYNC(db + 10240,      (const char*)bl + lh * 32,      16);
        CP_ASYNC(db + 10240 + 16, (const char*)bl + lh * 32 + 16, 16);
    };

    // warp tiling: warp_m in {0,1} (64 rows), warp_n in {0..3} (32 cols)
    const int wm = (wid & 1) * 64;
    const int wn = (wid >> 1) * 32;
    const uint32_t a_lo = (uint32_t)(lane & 15) * RS + (uint32_t)(lane >> 4) * 16;
    const uint32_t b_lo = (uint32_t)((lane & 7) + ((lane >> 4) << 3)) * RS
                        + (uint32_t)((lane >> 3) & 1) * 16;

    float acc[4][4][4] = {};

    issue_chunk(0);
    CP_COMMIT();

    for (int c = 0; c < nc; c++) {
        // wait for chunk c data, then ONE barrier. After the barrier it is
        // also safe to overwrite buf[(c+1)&1]: its last readers (compute of
        // chunk c-1) all reached this barrier already.
        CP_WAIT(0);
        __syncthreads();
        if (c + 1 < nc) { issue_chunk(c + 1); CP_COMMIT(); }

        const uint32_t base = sb + (c & 1) * STAGE_SZ;
        #pragma unroll
        for (int ks = 0; ks < 2; ks++) {
            // a-register reuse: aR holds aH for s0/s1, then aL for s2.
            uint32_t aR[4][4], bH[2][4], bL[2][4];
            #pragma unroll
            for (int bg = 0; bg < 2; bg++) {
                const uint32_t bd = base + 20480 + (uint32_t)(wn + bg * 16) * RS + ks * 32 + b_lo;
                LDM4(bH[bg], bd);
                LDM4(bL[bg], bd + 10240);
            }
            #pragma unroll
            for (int mi = 0; mi < 4; mi++) {
                const uint32_t ad = base + (uint32_t)(wm + mi * 16) * RS + ks * 32 + a_lo;
                LDM4(aR[mi], ad);
            }
            // s0: aH * bH
            #pragma unroll
            for (int mi = 0; mi < 4; mi++)
                #pragma unroll
                for (int nj = 0; nj < 4; nj++) {
                    const uint32_t* bf = &bH[nj >> 1][(nj & 1) * 2];
                    MMA(acc[mi][nj], aR[mi], bf[0], bf[1]);
                }
            // s1: aH * bL
            #pragma unroll
            for (int mi = 0; mi < 4; mi++)
                #pragma unroll
                for (int nj = 0; nj < 4; nj++) {
                    const uint32_t* bf = &bL[nj >> 1][(nj & 1) * 2];
                    MMA(acc[mi][nj], aR[mi], bf[0], bf[1]);
                }
            // reload aR with aL
            #pragma unroll
            for (int mi = 0; mi < 4; mi++) {
                const uint32_t ad = base + (uint32_t)(wm + mi * 16) * RS + ks * 32 + a_lo;
                LDM4(aR[mi], ad + 10240);
            }
            // s2: aL * bH
            #pragma unroll
            for (int mi = 0; mi < 4; mi++)
                #pragma unroll
                for (int nj = 0; nj < 4; nj++) {
                    const uint32_t* bf = &bH[nj >> 1][(nj & 1) * 2];
                    MMA(acc[mi][nj], aR[mi], bf[0], bf[1]);
                }
        }
    }

    // ---- epilogue ----
    #pragma unroll
    for (int mi = 0; mi < 4; mi++) {
        #pragma unroll
        for (int h2 = 0; h2 < 2; h2++) {
            const int r = wm + mi * 16 + (lane >> 2) + h2 * 8;
            size_t orow;
            if (MODE == 2)
                orow = (size_t)((bB * 256 + gh0 + (r >> 4)) * 256 + gw0 + (r & 15));
            else
                orow = (size_t)(m0 + r);
            #pragma unroll
            for (int nj = 0; nj < 4; nj++) {
                const int n = n0 + wn + nj * 8 + (lane & 3) * 2;
                float v0 = acc[mi][nj][h2 * 2 + 0] + __ldg(&bias[n]);
                float v1 = acc[mi][nj][h2 * 2 + 1] + __ldg(&bias[n + 1]);
                if (EPI == 1) {
                    v0 = 0.5f * v0 * (1.0f + erff(v0 * 0.7071067811865476f));
                    v1 = 0.5f * v1 * (1.0f + erff(v1 * 0.7071067811865476f));
                }
                if (EPI == 3 || EPI == 4) {
                    v0 = v0 >= 0.f ? v0 : 0.01f * v0;
                    v1 = v1 >= 0.f ? v1 : 0.01f * v1;
                }
                if (EPI == 2) {
                    const float2 rv = *(const float2*)(res + orow * ldRes + n);
                    v0 += rv.x; v1 += rv.y;
                }
                if (EPI == 4) {
                    const float2 rv = *(const float2*)(res + orow * ldRes + n);
                    v0 += 2.f * rv.x; v1 += 2.f * rv.y;
                }
                if (WF)
                    *(float2*)(out + orow * ldo + n) = make_float2(v0, v1);
                if (WBF && n < ldob) {
                    float h0 = __bfloat162float(__float2bfloat16(v0));
                    float h1 = __bfloat162float(__float2bfloat16(v1));
                    *(uint32_t*)(obH + orow * ldob + n) = pack_bf2(v0, v1);
                    *(uint32_t*)(obL + orow * ldob + n) = pack_bf2(v0 - h0, v1 - h1);
                }
            }
        }
    }
}

// ---------------- LayerNorm (fp32 in, bf16 hi/lo out) ----------------
__global__ void __launch_bounds__(256) ln_k(
    const float* __restrict__ in, int stride,
    const float* __restrict__ g, const float* __restrict__ bta,
    __nv_bfloat16* __restrict__ oh, __nv_bfloat16* __restrict__ ol)
{
    const int token = blockIdx.x * 8 + (threadIdx.x >> 5);
    const int lane = threadIdx.x & 31;
    const float* p = in + (size_t)token * stride;
    float4 v = *(const float4*)(p + lane * 4);
    float s  = v.x + v.y + v.z + v.w;
    float sq = v.x * v.x + v.y * v.y + v.z * v.z + v.w * v.w;
    #pragma unroll
    for (int o = 16; o; o >>= 1) {
        s  += __shfl_xor_sync(0xffffffffu, s,  o);
        sq += __shfl_xor_sync(0xffffffffu, sq, o);
    }
    const float mu  = s * (1.0f / 128.0f);
    const float var = sq * (1.0f / 128.0f) - mu * mu;
    const float rs  = rsqrtf(var + 1e-5f);
    float4 gv = *(const float4*)(g + lane * 4);
    float4 bv = *(const float4*)(bta + lane * 4);
    float o0 = (v.x - mu) * rs * gv.x + bv.x;
    float o1 = (v.y - mu) * rs * gv.y + bv.y;
    float o2 = (v.z - mu) * rs * gv.z + bv.z;
    float o3 = (v.w - mu) * rs * gv.w + bv.w;
    float h0 = __bfloat162float(__float2bfloat16(o0));
    float h1 = __bfloat162float(__float2bfloat16(o1));
    float h2 = __bfloat162float(__float2bfloat16(o2));
    float h3 = __bfloat162float(__float2bfloat16(o3));
    const size_t off = (size_t)token * 128 + lane * 4;
    *(uint2*)(oh + off) = make_uint2(pack_bf2(o0, o1), pack_bf2(o2, o3));
    *(uint2*)(ol + off) = make_uint2(pack_bf2(o0 - h0, o1 - h1), pack_bf2(o2 - h2, o3 - h3));
}

// ---------------- windowed attention (fp32; bf16 hi/lo out) ----------------
__global__ void __launch_bounds__(256) attn_k(
    const float* __restrict__ qkv, const float* __restrict__ rpb,
    __nv_bfloat16* __restrict__ oh, __nv_bfloat16* __restrict__ ol)
{
    __shared__ float qs[64][32];
    __shared__ float ks[64][33];
    __shared__ float vs[64][33];
    __shared__ float Ps[64][65];
    __shared__ int pixS[64];
    __shared__ int ridS[64];

    const int tid = threadIdx.x;
    const int head = blockIdx.x & 3;
    const int w = (blockIdx.x >> 2) & 1023;
    const int b = blockIdx.x >> 12;
    const int wi = w >> 5, wj = w & 31;

    if (tid < 64) {
        const int ti = tid >> 3, tj = tid & 7;
        const int hh = wi * 8 + ti, ww = wj * 8 + tj;
        pixS[tid] = (b * 256 + ((hh + 4) & 255)) * 256 + ((ww + 4) & 255);
        const int rh = hh < 248 ? 0 : (hh < 252 ? 1 : 2);
        const int rw = ww < 248 ? 0 : (ww < 252 ? 1 : 2);
        ridS[tid] = rh * 3 + rw;
    }
    __syncthreads();

    const int ho = head * 32;
    for (int idx = tid; idx < 2048; idx += 256) {
        const int t = idx >> 5, d = idx & 31;
        const size_t base = (size_t)pixS[t] * 384 + ho + d;
        qs[t][d] = qkv[base];
        ks[t][d] = qkv[base + 128];
        vs[t][d] = qkv[base + 256];
    }
    __syncthreads();

    const int warp = tid >> 5, lane = tid & 31;
    #pragma unroll
    for (int rr = 0; rr < 8; rr++) {
        const int r = warp * 8 + rr;
        float s0 = 0.f, s1 = 0.f;
        #pragma unroll
        for (int d = 0; d < 32; d++) {
            const float qv = qs[r][d];
            s0 += qv * ks[lane][d];
            s1 += qv * ks[lane + 32][d];
        }
        const int ri = r >> 3, rj = r & 7;
        const int rid_r = ridS[r];
        {
            const int c = lane;
            const int rel = (ri - (c >> 3) + 7) * 15 + (rj - (c & 7) + 7);
            s0 = s0 * 0.17677669529663687f + rpb[rel * 4 + head];
            if (rid_r != ridS[c]) s0 -= 1e9f;
        }
        {
            const int c = lane + 32;
            const int rel = (ri - (c >> 3) + 7) * 15 + (rj - (c & 7) + 7);
            s1 = s1 * 0.17677669529663687f + rpb[rel * 4 + head];
            if (rid_r != ridS[c]) s1 -= 1e9f;
        }
        float mx = fmaxf(s0, s1);
        #pragma unroll
        for (int o = 16; o; o >>= 1) mx = fmaxf(mx, __shfl_xor_sync(0xffffffffu, mx, o));
        float e0 = expf(s0 - mx), e1 = expf(s1 - mx);
        float sm = e0 + e1;
        #pragma unroll
        for (int o = 16; o; o >>= 1) sm += __shfl_xor_sync(0xffffffffu, sm, o);
        const float inv = 1.0f / sm;
        Ps[r][lane] = e0 * inv;
        Ps[r][lane + 32] = e1 * inv;
    }
    __syncthreads();

    const int i = tid >> 2, d0 = (tid & 3) * 8;
    float acc[8] = {};
    #pragma unroll
    for (int j = 0; j < 64; j++) {
        const float p = Ps[i][j];
        #pragma unroll
        for (int dd = 0; dd < 8; dd++) acc[dd] += p * vs[j][d0 + dd];
    }
    const size_t ob = (size_t)pixS[i] * 128 + ho + d0;
    #pragma unroll
    for (int dd = 0; dd < 8; dd += 2) {
        float h0 = __bfloat162float(__float2bfloat16(acc[dd]));
        float h1 = __bfloat162float(__float2bfloat16(acc[dd + 1]));
        *(uint32_t*)(oh + ob + dd) = pack_bf2(acc[dd], acc[dd + 1]);
        *(uint32_t*)(ol + ob + dd) = pack_bf2(acc[dd] - h0, acc[dd + 1] - h1);
    }
}

// ===========================================================================
extern "C" void kernel_launch(void* const* d_in, const int* in_sizes, int n_in,
                              void* d_out, int out_size)
{
    const float* x    = (const float*)d_in[0];
    const float* c1w  = (const float*)d_in[1];
    const float* c1b  = (const float*)d_in[2];
    const float* rw1  = (const float*)d_in[3];
    const float* rb1  = (const float*)d_in[4];
    const float* rw2  = (const float*)d_in[5];
    const float* rb2  = (const float*)d_in[6];
    const float* ln1g = (const float*)d_in[7];
    const float* ln1b = (const float*)d_in[8];
    const float* qkvw = (const float*)d_in[9];
    const float* qkvb = (const float*)d_in[10];
    const float* rpb  = (const float*)d_in[11];
    const float* pw   = (const float*)d_in[12];
    const float* pb   = (const float*)d_in[13];
    const float* ln2g = (const float*)d_in[14];
    const float* ln2b = (const float*)d_in[15];
    const float* mw1  = (const float*)d_in[16];
    const float* mb1  = (const float*)d_in[17];
    const float* mw2  = (const float*)d_in[18];
    const float* mb2  = (const float*)d_in[19];
    const float* c2w  = (const float*)d_in[20];
    const float* c2b  = (const float*)d_in[21];
    float* out = (float*)d_out;

    float *y, *qkv, *t;
    __nv_bfloat16 *xh,*xl,*yh,*yl,*rh,*rl,*ch,*cl,*lh,*ll,*ah,*al,*uh,*ul,*th,*tl,*wth,*wtl;
    cudaGetSymbolAddress((void**)&y,   g_y);
    cudaGetSymbolAddress((void**)&qkv, g_qkv);
    cudaGetSymbolAddress((void**)&t,   g_t);
    cudaGetSymbolAddress((void**)&xh, g_xh); cudaGetSymbolAddress((void**)&xl, g_xl);
    cudaGetSymbolAddress((void**)&yh, g_yh); cudaGetSymbolAddress((void**)&yl, g_yl);
    cudaGetSymbolAddress((void**)&rh, g_rh); cudaGetSymbolAddress((void**)&rl, g_rl);
    cudaGetSymbolAddress((void**)&ch, g_ch); cudaGetSymbolAddress((void**)&cl, g_cl);
    cudaGetSymbolAddress((void**)&lh, g_lh); cudaGetSymbolAddress((void**)&ll, g_ll);
    cudaGetSymbolAddress((void**)&ah, g_ah); cudaGetSymbolAddress((void**)&al, g_al);
    cudaGetSymbolAddress((void**)&uh, g_uh); cudaGetSymbolAddress((void**)&ul, g_ul);
    cudaGetSymbolAddress((void**)&th, g_th); cudaGetSymbolAddress((void**)&tl, g_tl);
    cudaGetSymbolAddress((void**)&wth, g_wth); cudaGetSymbolAddress((void**)&wtl, g_wtl);

    // one-time objects (same work every call; creation only happens once,
    // before the first graph capture)
    static cudaStream_t s2 = nullptr;
    static cudaEvent_t evFork = nullptr, evJoin = nullptr;
    if (s2 == nullptr) {
        cudaStreamCreateWithFlags(&s2, cudaStreamNonBlocking);
        cudaEventCreateWithFlags(&evFork, cudaEventDisableTiming);
        cudaEventCreateWithFlags(&evJoin, cudaEventDisableTiming);
        cudaFuncSetAttribute(mm_k<0,0,1,1>, cudaFuncAttributeMaxDynamicSharedMemorySize, SMEM_TOTAL);
        cudaFuncSetAttribute(mm_k<2,3,0,1>, cudaFuncAttributeMaxDynamicSharedMemorySize, SMEM_TOTAL);
        cudaFuncSetAttribute(mm_k<2,4,0,1>, cudaFuncAttributeMaxDynamicSharedMemorySize, SMEM_TOTAL);
        cudaFuncSetAttribute(mm_k<0,0,1,0>, cudaFuncAttributeMaxDynamicSharedMemorySize, SMEM_TOTAL);
        cudaFuncSetAttribute(mm_k<0,2,1,0>, cudaFuncAttributeMaxDynamicSharedMemorySize, SMEM_TOTAL);
        cudaFuncSetAttribute(mm_k<0,1,0,1>, cudaFuncAttributeMaxDynamicSharedMemorySize, SMEM_TOTAL);
        cudaFuncSetAttribute(mm_k<0,2,0,1>, cudaFuncAttributeMaxDynamicSharedMemorySize, SMEM_TOTAL);
        cudaFuncSetAttribute(mm_k<1,2,1,0>, cudaFuncAttributeMaxDynamicSharedMemorySize, SMEM_TOTAL);
    }

    // 0a. weight prep
    PrepArgs pa;
    pa.src[0]=c1w; pa.K[0]=256;  pa.N[0]=256; pa.off[0]=OFF_C1;
    pa.src[1]=rw1; pa.K[1]=1152; pa.N[1]=128; pa.off[1]=OFF_RW1;
    pa.src[2]=rw2; pa.K[2]=1152; pa.N[2]=128; pa.off[2]=OFF_RW2;
    pa.src[3]=qkvw;pa.K[3]=128;  pa.N[3]=384; pa.off[3]=OFF_QKV;
    pa.src[4]=pw;  pa.K[4]=128;  pa.N[4]=128; pa.off[4]=OFF_PW;
    pa.src[5]=mw1; pa.K[5]=128;  pa.N[5]=512; pa.off[5]=OFF_MW1;
    pa.src[6]=mw2; pa.K[6]=512;  pa.N[6]=128; pa.off[6]=OFF_MW2;
    pa.src[7]=c2w; pa.K[7]=256;  pa.N[7]=256; pa.off[7]=OFF_C2;
    prep_k<<<dim3(576, 8), 256>>>(pa, wth, wtl);
    // 0b. convert x
    cvt_k<<<32768, 256>>>(x, xh, xl, M_TOK * 64);

    const int M = M_TOK;
    // 1. conv1x1 #1: y(fp32 [M,256]) + ybf(cols 0-127)
    mm_k<0,0,1,1><<<dim3(M/128, 2), 256, SMEM_TOTAL>>>(
        xh, xl, nullptr, nullptr, 256, wth+OFF_C1, wtl+OFF_C1, 256,
        c1b, nullptr, 0, y, 256, yh, yl, 128);

    // ---- fork: conv branch on s2, transformer branch on capture stream ----
    cudaEventRecord(evFork, 0);
    cudaStreamWaitEvent(s2, evFork, 0);

    // conv branch (s2)
    // 2. conv3x3 #1 + lrelu -> rbf
    mm_k<2,3,0,1><<<1024, 256, SMEM_TOTAL, s2>>>(
        yh, yl, nullptr, nullptr, 128, wth+OFF_RW1, wtl+OFF_RW1, 1152,
        rb1, nullptr, 0, nullptr, 0, rh, rl, 128);
    // 3. conv3x3 #2 + lrelu + 2*conv_x -> cxbf
    mm_k<2,4,0,1><<<1024, 256, SMEM_TOTAL, s2>>>(
        rh, rl, nullptr, nullptr, 128, wth+OFF_RW2, wtl+OFF_RW2, 1152,
        rb2, y, 256, nullptr, 0, ch, cl, 128);

    // transformer branch (capture stream)
    // 4. LN1 on trans_x -> lnbf
    ln_k<<<M/8, 256>>>(y + 128, 256, ln1g, ln1b, lh, ll);
    // 5. qkv (fp32)
    mm_k<0,0,1,0><<<dim3(M/128, 3), 256, SMEM_TOTAL>>>(
        lh, ll, nullptr, nullptr, 128, wth+OFF_QKV, wtl+OFF_QKV, 128,
        qkvb, nullptr, 0, qkv, 384, nullptr, nullptr, 0);
    // 6. attention -> attbf
    attn_k<<<8192, 256>>>(qkv, rpb, ah, al);
    // 7. proj + residual(trans_x) -> t (fp32)
    mm_k<0,2,1,0><<<dim3(M/128, 1), 256, SMEM_TOTAL>>>(
        ah, al, nullptr, nullptr, 128, wth+OFF_PW, wtl+OFF_PW, 128,
        pb, y + 128, 256, t, 128, nullptr, nullptr, 0);
    // 8. LN2 -> lnbf
    ln_k<<<M/8, 256>>>(t, 128, ln2g, ln2b, lh, ll);
    // 9. mlp1 + gelu -> ubf
    mm_k<0,1,0,1><<<dim3(M/128, 4), 256, SMEM_TOTAL>>>(
        lh, ll, nullptr, nullptr, 128, wth+OFF_MW1, wtl+OFF_MW1, 128,
        mb1, nullptr, 0, nullptr, 0, uh, ul, 512);
    // 10. mlp2 + residual(t) -> t2bf
    mm_k<0,2,0,1><<<dim3(M/128, 1), 256, SMEM_TOTAL>>>(
        uh, ul, nullptr, nullptr, 512, wth+OFF_MW2, wtl+OFF_MW2, 512,
        mb2, t, 128, nullptr, 0, th, tl, 128);

    // ---- join ----
    cudaEventRecord(evJoin, s2);
    cudaStreamWaitEvent(0, evJoin, 0);

    // 11. conv1x1 #2 on concat(cx,t2) + x -> out
    mm_k<1,2,1,0><<<dim3(M/128, 2), 256, SMEM_TOTAL>>>(
        ch, cl, th, tl, 0, wth+OFF_C2, wtl+OFF_C2, 256,
        c2b, x, 256, out, 256, nullptr, nullptr, 0);
}